// round 1
// baseline (speedup 1.0000x reference)
#include <cuda_runtime.h>
#include <cstddef>

// ---------------------------------------------------------------------------
// Problem constants
// ---------------------------------------------------------------------------
#define BB   2
#define SS   2048
#define DD   1024
#define HH   16
#define DHH  64
#define DMM  4096
#define BSS  (BB * SS)          // 4096 rows
#define QKVN (3 * DD)           // 3072
#define LN_EPS 1e-5f

// ---------------------------------------------------------------------------
// Scratch (static device globals; no allocations allowed)
// ---------------------------------------------------------------------------
__device__ float g_x1[BSS * DD];          // LN1 output            16 MB
__device__ float g_wqkv[DD * QKVN];       // packed QKV weights    12 MB
__device__ float g_bqkv[QKVN];            // packed QKV bias
__device__ float g_qkv[(size_t)BSS * QKVN]; // q|k|v activations   48 MB
__device__ float g_z[BSS * DD];           // attention output      16 MB
__device__ float g_rmid[BSS * DD];        // resid_mid             16 MB
__device__ float g_x2[BSS * DD];          // LN2 output            16 MB
__device__ float g_h[(size_t)BSS * DMM];  // MLP hidden            64 MB

// ---------------------------------------------------------------------------
// Repack W_Q/W_K/W_V [H,D,DH] -> [D, 3D] (col = h*64+dh | +1024 | +2048)
// ---------------------------------------------------------------------------
__global__ void repack_qkv(const float* __restrict__ WQ,
                           const float* __restrict__ WK,
                           const float* __restrict__ WV,
                           const float* __restrict__ bQ,
                           const float* __restrict__ bK,
                           const float* __restrict__ bV) {
    int idx = blockIdx.x * blockDim.x + threadIdx.x;
    if (idx < DD * DD) {
        int k = idx / DD;      // 0..1023 (d dimension)
        int n = idx % DD;      // 0..1023 (= h*64+dh)
        int h = n >> 6;
        int dh = n & 63;
        int src = h * DD * DHH + k * DHH + dh;
        g_wqkv[k * QKVN + n]            = WQ[src];
        g_wqkv[k * QKVN + DD + n]       = WK[src];
        g_wqkv[k * QKVN + 2 * DD + n]   = WV[src];
    }
    if (idx < DD) {
        g_bqkv[idx]          = bQ[idx];
        g_bqkv[DD + idx]     = bK[idx];
        g_bqkv[2 * DD + idx] = bV[idx];
    }
}

// ---------------------------------------------------------------------------
// Block reduction helper
// ---------------------------------------------------------------------------
__device__ __forceinline__ float block_sum(float v, float* red) {
    __syncthreads();
    int lane = threadIdx.x & 31;
    int wid  = threadIdx.x >> 5;
    #pragma unroll
    for (int o = 16; o > 0; o >>= 1) v += __shfl_xor_sync(0xffffffffu, v, o);
    if (lane == 0) red[wid] = v;
    __syncthreads();
    float t = (threadIdx.x < (blockDim.x >> 5)) ? red[threadIdx.x] : 0.f;
    if (wid == 0) {
        #pragma unroll
        for (int o = 16; o > 0; o >>= 1) t += __shfl_xor_sync(0xffffffffu, t, o);
        if (lane == 0) red[0] = t;
    }
    __syncthreads();
    return red[0];
}

// ---------------------------------------------------------------------------
// LayerNorm (TransformerLens style): center, scale = sqrt(mean(x_c^2)+eps)
// ---------------------------------------------------------------------------
__global__ __launch_bounds__(256)
void ln_kernel(const float* __restrict__ x, const float* __restrict__ w,
               const float* __restrict__ b, float* __restrict__ out) {
    __shared__ float row[DD];
    __shared__ float red[32];
    int r = blockIdx.x;
    const float* xr = x + (size_t)r * DD;
    float s = 0.f;
    for (int i = threadIdx.x; i < DD; i += 256) { float v = xr[i]; row[i] = v; s += v; }
    s = block_sum(s, red);
    float mean = s * (1.f / DD);
    float q = 0.f;
    for (int i = threadIdx.x; i < DD; i += 256) { float v = row[i] - mean; q += v * v; }
    q = block_sum(q, red);
    float inv = rsqrtf(q * (1.f / DD) + LN_EPS);
    float* o = out + (size_t)r * DD;
    for (int i = threadIdx.x; i < DD; i += 256)
        o[i] = (row[i] - mean) * inv * w[i] + b[i];
}

// ---------------------------------------------------------------------------
// GELU (tanh approx, gelu_new)
// ---------------------------------------------------------------------------
__device__ __forceinline__ float gelu_tanh(float x) {
    float x3 = x * x * x;
    return 0.5f * x * (1.f + tanhf(0.7978845608028654f * (x + 0.044715f * x3)));
}

// ---------------------------------------------------------------------------
// SGEMM: C[M,N] = A[M,K] @ B[K,N] + bias[N]   (all row-major)
// EPI: 0 = bias only, 1 = bias + gelu, 2 = bias + residual add (R[M,N])
// 128x128 tile, BK=8, 256 threads, 8x8 per thread. Dims must divide tiles.
// ---------------------------------------------------------------------------
template <int EPI>
__global__ __launch_bounds__(256)
void sgemm128(const float* __restrict__ A, const float* __restrict__ B,
              const float* __restrict__ bias, const float* __restrict__ R,
              float* __restrict__ C, int M, int N, int K) {
    const int BM = 128, BN = 128, BK = 8, TM = 8, TN = 8;
    __shared__ float As[BK][BM];
    __shared__ float Bs[BK][BN];

    int tid = threadIdx.x;
    int cRow = blockIdx.y, cCol = blockIdx.x;

    const float* Ab = A + (size_t)cRow * BM * K;
    const float* Bb = B + (size_t)cCol * BN;

    const int threadCol = tid % (BN / TN);   // 0..15
    const int threadRow = tid / (BN / TN);   // 0..15
    const int innerRowA = tid / (BK / 4);    // 0..127
    const int innerColA = tid % (BK / 4);    // 0..1
    const int innerRowB = tid / (BN / 4);    // 0..7
    const int innerColB = tid % (BN / 4);    // 0..31

    float acc[TM][TN];
    #pragma unroll
    for (int m = 0; m < TM; m++)
        #pragma unroll
        for (int n = 0; n < TN; n++) acc[m][n] = 0.f;

    float regM[TM], regN[TN];

    for (int k0 = 0; k0 < K; k0 += BK) {
        float4 a4 = *(const float4*)(Ab + (size_t)innerRowA * K + innerColA * 4);
        As[innerColA * 4 + 0][innerRowA] = a4.x;
        As[innerColA * 4 + 1][innerRowA] = a4.y;
        As[innerColA * 4 + 2][innerRowA] = a4.z;
        As[innerColA * 4 + 3][innerRowA] = a4.w;
        *(float4*)(&Bs[innerRowB][innerColB * 4]) =
            *(const float4*)(Bb + (size_t)innerRowB * N + innerColB * 4);
        __syncthreads();
        Ab += BK;
        Bb += (size_t)BK * N;
        #pragma unroll
        for (int k = 0; k < BK; k++) {
            #pragma unroll
            for (int m = 0; m < TM; m++) regM[m] = As[k][threadRow * TM + m];
            #pragma unroll
            for (int n = 0; n < TN; n++) regN[n] = Bs[k][threadCol * TN + n];
            #pragma unroll
            for (int m = 0; m < TM; m++)
                #pragma unroll
                for (int n = 0; n < TN; n++) acc[m][n] += regM[m] * regN[n];
        }
        __syncthreads();
    }

    int rowBase = cRow * BM + threadRow * TM;
    int colBase = cCol * BN + threadCol * TN;
    #pragma unroll
    for (int m = 0; m < TM; m++) {
        int row = rowBase + m;
        #pragma unroll
        for (int n = 0; n < TN; n += 4) {
            int col = colBase + n;
            float4 v;
            v.x = acc[m][n + 0] + bias[col + 0];
            v.y = acc[m][n + 1] + bias[col + 1];
            v.z = acc[m][n + 2] + bias[col + 2];
            v.w = acc[m][n + 3] + bias[col + 3];
            if (EPI == 1) {
                v.x = gelu_tanh(v.x); v.y = gelu_tanh(v.y);
                v.z = gelu_tanh(v.z); v.w = gelu_tanh(v.w);
            } else if (EPI == 2) {
                const float4 r4 = *(const float4*)(R + (size_t)row * N + col);
                v.x += r4.x; v.y += r4.y; v.z += r4.z; v.w += r4.w;
            }
            *(float4*)(C + (size_t)row * N + col) = v;
        }
    }
}

// ---------------------------------------------------------------------------
// Flash attention, fp32, causal. Block = (qt 64-row tile, head, batch).
// smem tiles (transposed where column access is needed), 4x4 per thread.
// ---------------------------------------------------------------------------
#define SPAD 68
#define FLASH_SMEM (4 * 64 * SPAD * (int)sizeof(float))

__global__ __launch_bounds__(256)
void flash_kernel(const float* __restrict__ qkv, float* __restrict__ z) {
    extern __shared__ float sm[];
    float* qs = sm;                   // qs[k][r]  (transposed)
    float* ks = sm + 64 * SPAD;       // ks[k][c]  (transposed)
    float* vs = sm + 2 * 64 * SPAD;   // vs[j][c]
    float* ps = sm + 3 * 64 * SPAD;   // ps[j][r]  (transposed)

    const int qt = blockIdx.x, h = blockIdx.y, b = blockIdx.z;
    const int tid = threadIdx.x;
    const int tx = tid & 15, ty = tid >> 4;
    const int r0 = ty * 4, c0 = tx * 4;

    const float* base = qkv + (size_t)b * SS * QKVN;

    // load Q tile transposed
    #pragma unroll
    for (int it = 0; it < 4; it++) {
        int i = tid + it * 256;       // float4 index, 0..1023
        int row = i >> 4;
        int c4 = (i & 15) * 4;
        float4 v = *(const float4*)(base + (size_t)(qt * 64 + row) * QKVN + h * 64 + c4);
        qs[(c4 + 0) * SPAD + row] = v.x;
        qs[(c4 + 1) * SPAD + row] = v.y;
        qs[(c4 + 2) * SPAD + row] = v.z;
        qs[(c4 + 3) * SPAD + row] = v.w;
    }

    float m_i[4], l_i[4], o[4][4];
    #pragma unroll
    for (int i = 0; i < 4; i++) {
        m_i[i] = -1e30f; l_i[i] = 0.f;
        #pragma unroll
        for (int j = 0; j < 4; j++) o[i][j] = 0.f;
    }
    __syncthreads();

    for (int kt = 0; kt <= qt; kt++) {
        // load K tile (transposed) + V tile
        #pragma unroll
        for (int it = 0; it < 4; it++) {
            int i = tid + it * 256;
            int row = i >> 4;
            int c4 = (i & 15) * 4;
            const float* kr = base + (size_t)(kt * 64 + row) * QKVN + h * 64;
            float4 kv = *(const float4*)(kr + DD + c4);
            ks[(c4 + 0) * SPAD + row] = kv.x;
            ks[(c4 + 1) * SPAD + row] = kv.y;
            ks[(c4 + 2) * SPAD + row] = kv.z;
            ks[(c4 + 3) * SPAD + row] = kv.w;
            *(float4*)(vs + row * SPAD + c4) = *(const float4*)(kr + 2 * DD + c4);
        }
        __syncthreads();

        // scores: s[i][j] = sum_k q[r0+i][k] * k[c0+j][k]
        float s[4][4];
        #pragma unroll
        for (int i = 0; i < 4; i++)
            #pragma unroll
            for (int j = 0; j < 4; j++) s[i][j] = 0.f;
        #pragma unroll 4
        for (int k = 0; k < 64; k++) {
            float qv[4], kv[4];
            #pragma unroll
            for (int i = 0; i < 4; i++) qv[i] = qs[k * SPAD + r0 + i];
            #pragma unroll
            for (int j = 0; j < 4; j++) kv[j] = ks[k * SPAD + c0 + j];
            #pragma unroll
            for (int i = 0; i < 4; i++)
                #pragma unroll
                for (int j = 0; j < 4; j++) s[i][j] += qv[i] * kv[j];
        }

        // scale + causal mask (only diagonal tile needs masking)
        if (kt == qt) {
            #pragma unroll
            for (int i = 0; i < 4; i++)
                #pragma unroll
                for (int j = 0; j < 4; j++)
                    s[i][j] = (c0 + j <= r0 + i) ? s[i][j] * 0.125f : -1e30f;
        } else {
            #pragma unroll
            for (int i = 0; i < 4; i++)
                #pragma unroll
                for (int j = 0; j < 4; j++) s[i][j] *= 0.125f;
        }

        // online softmax row stats (reduce across the 16 tx lanes)
        float mnew[4], rsum[4];
        #pragma unroll
        for (int i = 0; i < 4; i++) {
            float mx = fmaxf(fmaxf(s[i][0], s[i][1]), fmaxf(s[i][2], s[i][3]));
            #pragma unroll
            for (int off = 1; off < 16; off <<= 1)
                mx = fmaxf(mx, __shfl_xor_sync(0xffffffffu, mx, off));
            mnew[i] = fmaxf(m_i[i], mx);
        }
        #pragma unroll
        for (int i = 0; i < 4; i++) {
            float rs = 0.f;
            #pragma unroll
            for (int j = 0; j < 4; j++) {
                s[i][j] = __expf(s[i][j] - mnew[i]);
                rs += s[i][j];
            }
            #pragma unroll
            for (int off = 1; off < 16; off <<= 1)
                rs += __shfl_xor_sync(0xffffffffu, rs, off);
            rsum[i] = rs;
        }
        #pragma unroll
        for (int i = 0; i < 4; i++) {
            float alpha = __expf(m_i[i] - mnew[i]);
            l_i[i] = l_i[i] * alpha + rsum[i];
            m_i[i] = mnew[i];
            #pragma unroll
            for (int j = 0; j < 4; j++) o[i][j] *= alpha;
        }

        // stage P transposed
        #pragma unroll
        for (int i = 0; i < 4; i++)
            #pragma unroll
            for (int j = 0; j < 4; j++)
                ps[(c0 + j) * SPAD + r0 + i] = s[i][j];
        __syncthreads();

        // o += P @ V
        #pragma unroll 4
        for (int j = 0; j < 64; j++) {
            float pr[4], vv[4];
            #pragma unroll
            for (int i = 0; i < 4; i++) pr[i] = ps[j * SPAD + r0 + i];
            #pragma unroll
            for (int jj = 0; jj < 4; jj++) vv[jj] = vs[j * SPAD + c0 + jj];
            #pragma unroll
            for (int i = 0; i < 4; i++)
                #pragma unroll
                for (int jj = 0; jj < 4; jj++) o[i][jj] += pr[i] * vv[jj];
        }
        __syncthreads();
    }

    // write z[b, qrow, h, :]
    #pragma unroll
    for (int i = 0; i < 4; i++) {
        float invl = 1.f / l_i[i];
        size_t row = (size_t)(b * SS + qt * 64 + r0 + i);
        float4 v;
        v.x = o[i][0] * invl; v.y = o[i][1] * invl;
        v.z = o[i][2] * invl; v.w = o[i][3] * invl;
        *(float4*)(z + row * DD + h * 64 + c0) = v;
    }
}

// ---------------------------------------------------------------------------
// Launch
// ---------------------------------------------------------------------------
extern "C" void kernel_launch(void* const* d_in, const int* in_sizes, int n_in,
                              void* d_out, int out_size) {
    (void)in_sizes; (void)n_in; (void)out_size;
    const float* resid_pre = (const float*)d_in[0];
    const float* ln1_w = (const float*)d_in[1];
    const float* ln1_b = (const float*)d_in[2];
    const float* W_Q   = (const float*)d_in[3];
    const float* W_K   = (const float*)d_in[4];
    const float* W_V   = (const float*)d_in[5];
    const float* W_O   = (const float*)d_in[6];
    const float* b_Q   = (const float*)d_in[7];
    const float* b_K   = (const float*)d_in[8];
    const float* b_V   = (const float*)d_in[9];
    const float* b_O   = (const float*)d_in[10];
    const float* ln2_w = (const float*)d_in[11];
    const float* ln2_b = (const float*)d_in[12];
    const float* W_in  = (const float*)d_in[13];
    const float* b_in  = (const float*)d_in[14];
    const float* W_out = (const float*)d_in[15];
    const float* b_out = (const float*)d_in[16];
    float* out = (float*)d_out;

    float *p_x1, *p_wqkv, *p_bqkv, *p_qkv, *p_z, *p_rmid, *p_x2, *p_h;
    cudaGetSymbolAddress((void**)&p_x1,   g_x1);
    cudaGetSymbolAddress((void**)&p_wqkv, g_wqkv);
    cudaGetSymbolAddress((void**)&p_bqkv, g_bqkv);
    cudaGetSymbolAddress((void**)&p_qkv,  g_qkv);
    cudaGetSymbolAddress((void**)&p_z,    g_z);
    cudaGetSymbolAddress((void**)&p_rmid, g_rmid);
    cudaGetSymbolAddress((void**)&p_x2,   g_x2);
    cudaGetSymbolAddress((void**)&p_h,    g_h);

    // 1. repack QKV weights + biases
    repack_qkv<<<(DD * DD + 255) / 256, 256>>>(W_Q, W_K, W_V, b_Q, b_K, b_V);

    // 2. LN1
    ln_kernel<<<BSS, 256>>>(resid_pre, ln1_w, ln1_b, p_x1);

    // 3. QKV projection: [4096,1024] @ [1024,3072]
    sgemm128<0><<<dim3(QKVN / 128, BSS / 128), 256>>>(
        p_x1, p_wqkv, p_bqkv, nullptr, p_qkv, BSS, QKVN, DD);

    // 4. flash attention
    cudaFuncSetAttribute(flash_kernel,
                         cudaFuncAttributeMaxDynamicSharedMemorySize, FLASH_SMEM);
    flash_kernel<<<dim3(SS / 64, HH, BB), 256, FLASH_SMEM>>>(p_qkv, p_z);

    // 5. O projection + residual: resid_mid = resid_pre + z @ W_O + b_O
    sgemm128<2><<<dim3(DD / 128, BSS / 128), 256>>>(
        p_z, W_O, b_O, resid_pre, p_rmid, BSS, DD, DD);

    // 6. LN2
    ln_kernel<<<BSS, 256>>>(p_rmid, ln2_w, ln2_b, p_x2);

    // 7. MLP in + gelu: [4096,1024] @ [1024,4096]
    sgemm128<1><<<dim3(DMM / 128, BSS / 128), 256>>>(
        p_x2, W_in, b_in, nullptr, p_h, BSS, DMM, DD);

    // 8. MLP out + residual -> d_out: [4096,4096] @ [4096,1024]
    sgemm128<2><<<dim3(DD / 128, BSS / 128), 256>>>(
        p_h, W_out, b_out, p_rmid, out, BSS, DD, DMM);
}

// round 4
// speedup vs baseline: 2.0956x; 2.0956x over previous
#include <cuda_runtime.h>
#include <cuda_fp16.h>
#include <cstdint>
#include <cstddef>

// ---------------------------------------------------------------------------
// Problem constants
// ---------------------------------------------------------------------------
#define BB   2
#define SS   2048
#define DD   1024
#define HH   16
#define DHH  64
#define DMM  4096
#define BSS  (BB * SS)          // 4096 rows
#define QKVN (3 * DD)           // 3072
#define LN_EPS 1e-5f

// ---------------------------------------------------------------------------
// Scratch (static device globals; no allocations allowed)
// ---------------------------------------------------------------------------
__device__ __half g_x1h[BSS * DD], g_x1l[BSS * DD];
__device__ __half g_wqkvh[QKVN * DD], g_wqkvl[QKVN * DD];   // [N=3072,K=1024]
__device__ float  g_bqkv[QKVN];
__device__ float  g_qkv[(size_t)BSS * QKVN];                // fp32 for flash
__device__ __half g_zh[BSS * DD], g_zl[BSS * DD];
__device__ __half g_woh[DD * DD], g_wol[DD * DD];           // [N=1024,K=1024]
__device__ float  g_rmid[BSS * DD];
__device__ __half g_x2h[BSS * DD], g_x2l[BSS * DD];
__device__ __half g_winh[DMM * DD], g_winl[DMM * DD];       // [N=4096,K=1024]
__device__ __half g_hh[(size_t)BSS * DMM], g_hl[(size_t)BSS * DMM];
__device__ __half g_wouth[DD * DMM], g_woutl[DD * DMM];     // [N=1024,K=4096]

// ---------------------------------------------------------------------------
// PTX helpers (baseline ISA only: ldmatrix / mma.sync / cp.async)
// ---------------------------------------------------------------------------
__device__ __forceinline__ uint32_t smem_u32(const void* p) {
    uint32_t a;
    asm("{ .reg .u64 t; cvta.to.shared.u64 t, %1; cvt.u32.u64 %0, t; }" : "=r"(a) : "l"(p));
    return a;
}
__device__ __forceinline__ void ldsm4(uint32_t& r0, uint32_t& r1, uint32_t& r2,
                                      uint32_t& r3, uint32_t a) {
    asm volatile("ldmatrix.sync.aligned.m8n8.x4.shared.b16 {%0,%1,%2,%3}, [%4];"
                 : "=r"(r0), "=r"(r1), "=r"(r2), "=r"(r3) : "r"(a));
}
__device__ __forceinline__ void mma16816(float* c, const uint32_t* a, const uint32_t* b) {
    asm volatile(
        "mma.sync.aligned.m16n8k16.row.col.f32.f16.f16.f32 "
        "{%0,%1,%2,%3},{%4,%5,%6,%7},{%8,%9},{%0,%1,%2,%3};"
        : "+f"(c[0]), "+f"(c[1]), "+f"(c[2]), "+f"(c[3])
        : "r"(a[0]), "r"(a[1]), "r"(a[2]), "r"(a[3]), "r"(b[0]), "r"(b[1]));
}
__device__ __forceinline__ void cp16(uint32_t d, const void* s) {
    asm volatile("cp.async.cg.shared.global [%0], [%1], 16;" :: "r"(d), "l"(s) : "memory");
}
#define CP_COMMIT() asm volatile("cp.async.commit_group;" ::: "memory")

__device__ __forceinline__ void split_h(float x, __half& hi, __half& lo) {
    hi = __float2half_rn(x);
    lo = __float2half_rn(x - __half2float(hi));
}

// ---------------------------------------------------------------------------
// Weight conversion kernels
// ---------------------------------------------------------------------------
// W_Q/K/V [H,D,DH] -> wqkv [N=3072,K=1024] fp16 hi/lo. block 256, grid (32 ktiles, 16 h)
__global__ __launch_bounds__(256)
void conv_wqkv(const float* __restrict__ WQ, const float* __restrict__ WK,
               const float* __restrict__ WV) {
    __shared__ float t[32][65];
    int h = blockIdx.y, k0 = blockIdx.x * 32, tid = threadIdx.x;
    const float* Ws[3] = {WQ, WK, WV};
    for (int s = 0; s < 3; s++) {
        const float* src = Ws[s] + (size_t)h * DD * DHH + (size_t)k0 * DHH;
        #pragma unroll
        for (int it = 0; it < 8; it++) {
            int idx = tid + it * 256;
            t[idx >> 6][idx & 63] = src[idx];
        }
        __syncthreads();
        #pragma unroll
        for (int it = 0; it < 8; it++) {
            int idx = tid + it * 256;
            int dh = idx >> 5, kk = idx & 31;
            float v = t[kk][dh];
            __half hi, lo; split_h(v, hi, lo);
            size_t n = (size_t)s * DD + h * 64 + dh;
            g_wqkvh[n * DD + k0 + kk] = hi;
            g_wqkvl[n * DD + k0 + kk] = lo;
        }
        __syncthreads();
    }
}

__global__ void pack_bqkv(const float* __restrict__ bQ, const float* __restrict__ bK,
                          const float* __restrict__ bV) {
    int i = blockIdx.x * blockDim.x + threadIdx.x;
    if (i < DD) {
        g_bqkv[i] = bQ[i];
        g_bqkv[DD + i] = bK[i];
        g_bqkv[2 * DD + i] = bV[i];
    }
}

// transpose+split: W fp32 [K,N] -> Bh/Bl fp16 [N,K]. block (32,8), grid (N/32, K/32)
__global__ __launch_bounds__(256)
void conv_wT(const float* __restrict__ W, __half* __restrict__ Bh,
             __half* __restrict__ Bl, int K, int N) {
    __shared__ float t[32][33];
    int n0 = blockIdx.x * 32, k0 = blockIdx.y * 32;
    int tx = threadIdx.x, ty = threadIdx.y;
    #pragma unroll
    for (int i = 0; i < 4; i++)
        t[ty + i * 8][tx] = W[(size_t)(k0 + ty + i * 8) * N + n0 + tx];
    __syncthreads();
    #pragma unroll
    for (int i = 0; i < 4; i++) {
        int n = n0 + ty + i * 8, k = k0 + tx;
        float v = t[tx][ty + i * 8];
        __half hi, lo; split_h(v, hi, lo);
        Bh[(size_t)n * K + k] = hi;
        Bl[(size_t)n * K + k] = lo;
    }
}

// ---------------------------------------------------------------------------
// LayerNorm -> fp16 hi/lo
// ---------------------------------------------------------------------------
__device__ __forceinline__ float block_sum(float v, float* red) {
    __syncthreads();
    int lane = threadIdx.x & 31, wid = threadIdx.x >> 5;
    #pragma unroll
    for (int o = 16; o > 0; o >>= 1) v += __shfl_xor_sync(0xffffffffu, v, o);
    if (lane == 0) red[wid] = v;
    __syncthreads();
    float t = (threadIdx.x < (blockDim.x >> 5)) ? red[threadIdx.x] : 0.f;
    if (wid == 0) {
        #pragma unroll
        for (int o = 16; o > 0; o >>= 1) t += __shfl_xor_sync(0xffffffffu, t, o);
        if (lane == 0) red[0] = t;
    }
    __syncthreads();
    return red[0];
}

__global__ __launch_bounds__(256)
void ln_kernel(const float* __restrict__ x, const float* __restrict__ w,
               const float* __restrict__ b, __half* __restrict__ oh,
               __half* __restrict__ ol) {
    __shared__ float row[DD];
    __shared__ float red[32];
    int r = blockIdx.x;
    const float* xr = x + (size_t)r * DD;
    float s = 0.f;
    for (int i = threadIdx.x; i < DD; i += 256) { float v = xr[i]; row[i] = v; s += v; }
    s = block_sum(s, red);
    float mean = s * (1.f / DD);
    float q = 0.f;
    for (int i = threadIdx.x; i < DD; i += 256) { float v = row[i] - mean; q += v * v; }
    q = block_sum(q, red);
    float inv = rsqrtf(q * (1.f / DD) + LN_EPS);
    for (int i = threadIdx.x; i < DD; i += 256) {
        float y = (row[i] - mean) * inv * w[i] + b[i];
        __half hi, lo; split_h(y, hi, lo);
        oh[(size_t)r * DD + i] = hi;
        ol[(size_t)r * DD + i] = lo;
    }
}

// ---------------------------------------------------------------------------
// GELU (tanh approx)
// ---------------------------------------------------------------------------
__device__ __forceinline__ float gelu_tanh(float x) {
    float x3 = x * x * x;
    return 0.5f * x * (1.f + tanhf(0.7978845608028654f * (x + 0.044715f * x3)));
}

// ---------------------------------------------------------------------------
// HMMA fp16-split GEMM: C[M,N] = (Ah+Al)[M,K] @ (Bh+Bl)[N,K]^T + bias
// 3 MMA terms: AhBh + AhBl + AlBh (AlBl ~2^-22, dropped). fp32 accumulate.
// 128x128 CTA tile, K-tile 32, 8 warps (2x4), warp tile 64x32, m16n8k16.
// smem rows padded to 80B -> 8-row ldmatrix chunks hit 8 distinct 16B slots.
// K-tile row layout: 32 halves = 64 bytes; k16 chunk kk at byte kk*32,
// k8 sub-chunk at +0/+16.
// EPI: 0 = bias -> fp32 ; 1 = bias+gelu -> fp16 hi/lo ; 2 = bias+residual -> fp32
// ---------------------------------------------------------------------------
#define OPD_BYTES 10240              // 128 rows * 80 B
#define BUF_BYTES (4 * OPD_BYTES)    // Ah | Al | Bh | Bl
#define GEMM_SMEM (2 * BUF_BYTES)    // double buffered: 81920 B

template <int EPI>
__global__ __launch_bounds__(256, 2)
void gemm_hmma(const __half* __restrict__ Ah, const __half* __restrict__ Al,
               const __half* __restrict__ Bh, const __half* __restrict__ Bl,
               const float* __restrict__ bias, const float* __restrict__ R,
               float* __restrict__ Cf, __half* __restrict__ Chi,
               __half* __restrict__ Clo, int M, int N, int K) {
    extern __shared__ char sm[];
    const uint32_t sb = smem_u32(sm);
    const int tid = threadIdx.x;
    const int wid = tid >> 5, lid = tid & 31;
    const int warp_m = wid >> 2, warp_n = wid & 3;

    const char* src[4];
    src[0] = (const char*)(Ah + (size_t)blockIdx.y * 128 * K);
    src[1] = (const char*)(Al + (size_t)blockIdx.y * 128 * K);
    src[2] = (const char*)(Bh + (size_t)blockIdx.x * 128 * K);
    src[3] = (const char*)(Bl + (size_t)blockIdx.x * 128 * K);
    const size_t rowB = (size_t)K * 2;

    // per-lane ldmatrix address components (x4: lanes g=0..3 address matrices 0..3)
    const int g = lid >> 3, li = lid & 7;
    const int a_row = (g & 1) * 8 + li, a_kb = (g >> 1) * 16;
    const int b_row = (g >> 1) * 8 + li, b_kb = (g & 1) * 16;

    float acc[4][4][4];
    #pragma unroll
    for (int mt = 0; mt < 4; mt++)
        #pragma unroll
        for (int nt = 0; nt < 4; nt++)
            #pragma unroll
            for (int e = 0; e < 4; e++) acc[mt][nt][e] = 0.f;

    const int T = K >> 5;

    // prologue: issue K-tiles 0 and 1
    #pragma unroll
    for (int pre = 0; pre < 2; pre++) {
        uint32_t dst = sb + pre * BUF_BYTES;
        int k0b = pre * 64;
        #pragma unroll
        for (int it = 0; it < 8; it++) {
            int c = tid + it * 256;
            int o = c >> 9, r = c & 511, row = r >> 2, kc = r & 3;
            cp16(dst + o * OPD_BYTES + row * 80 + kc * 16,
                 src[o] + (size_t)row * rowB + k0b + kc * 16);
        }
        CP_COMMIT();
    }

    for (int t = 0; t < T; t++) {
        if (t + 1 < T) { asm volatile("cp.async.wait_group 1;" ::: "memory"); }
        else           { asm volatile("cp.async.wait_group 0;" ::: "memory"); }
        __syncthreads();

        uint32_t buf = sb + (t & 1) * BUF_BYTES;
        uint32_t aH = buf + (warp_m * 64 + a_row) * 80 + a_kb;
        uint32_t aL = aH + OPD_BYTES;
        uint32_t bH = buf + 2 * OPD_BYTES + (warp_n * 32 + b_row) * 80 + b_kb;
        uint32_t bL = bH + OPD_BYTES;

        #pragma unroll
        for (int kk = 0; kk < 2; kk++) {
            uint32_t bh[4][2], bl[4][2];
            ldsm4(bh[0][0], bh[0][1], bh[1][0], bh[1][1], bH + kk * 32);
            ldsm4(bh[2][0], bh[2][1], bh[3][0], bh[3][1], bH + 16 * 80 + kk * 32);
            ldsm4(bl[0][0], bl[0][1], bl[1][0], bl[1][1], bL + kk * 32);
            ldsm4(bl[2][0], bl[2][1], bl[3][0], bl[3][1], bL + 16 * 80 + kk * 32);
            #pragma unroll
            for (int mt = 0; mt < 4; mt++) {
                uint32_t ah[4], al[4];
                ldsm4(ah[0], ah[1], ah[2], ah[3], aH + mt * 16 * 80 + kk * 32);
                ldsm4(al[0], al[1], al[2], al[3], aL + mt * 16 * 80 + kk * 32);
                #pragma unroll
                for (int nt = 0; nt < 4; nt++) {
                    mma16816(acc[mt][nt], ah, bh[nt]);
                    mma16816(acc[mt][nt], ah, bl[nt]);
                    mma16816(acc[mt][nt], al, bh[nt]);
                }
            }
        }
        __syncthreads();

        if (t + 2 < T) {
            uint32_t dst = sb + (t & 1) * BUF_BYTES;
            int k0b = (t + 2) * 64;
            #pragma unroll
            for (int it = 0; it < 8; it++) {
                int c = tid + it * 256;
                int o = c >> 9, r = c & 511, row = r >> 2, kc = r & 3;
                cp16(dst + o * OPD_BYTES + row * 80 + kc * 16,
                     src[o] + (size_t)row * rowB + k0b + kc * 16);
            }
            CP_COMMIT();
        }
    }

    // ---- epilogue ----
    const int group = lid >> 2, t4 = lid & 3;
    const size_t rbase = (size_t)blockIdx.y * 128 + warp_m * 64;
    const int cbase = blockIdx.x * 128 + warp_n * 32;
    #pragma unroll
    for (int mt = 0; mt < 4; mt++) {
        size_t r0 = rbase + mt * 16 + group;
        size_t r1 = r0 + 8;
        #pragma unroll
        for (int nt = 0; nt < 4; nt++) {
            int col = cbase + nt * 8 + t4 * 2;
            float* c = acc[mt][nt];
            float b0 = bias[col], b1 = bias[col + 1];
            float x0 = c[0] + b0, x1 = c[1] + b1;
            float x2 = c[2] + b0, x3 = c[3] + b1;
            if (EPI == 1) {
                x0 = gelu_tanh(x0); x1 = gelu_tanh(x1);
                x2 = gelu_tanh(x2); x3 = gelu_tanh(x3);
                __half h0, l0, h1, l1, h2, l2, h3, l3;
                split_h(x0, h0, l0); split_h(x1, h1, l1);
                split_h(x2, h2, l2); split_h(x3, h3, l3);
                *(__half2*)(Chi + r0 * N + col) = __halves2half2(h0, h1);
                *(__half2*)(Clo + r0 * N + col) = __halves2half2(l0, l1);
                *(__half2*)(Chi + r1 * N + col) = __halves2half2(h2, h3);
                *(__half2*)(Clo + r1 * N + col) = __halves2half2(l2, l3);
            } else {
                if (EPI == 2) {
                    float2 ra = *(const float2*)(R + r0 * N + col);
                    float2 rb = *(const float2*)(R + r1 * N + col);
                    x0 += ra.x; x1 += ra.y; x2 += rb.x; x3 += rb.y;
                }
                float2 va; va.x = x0; va.y = x1;
                float2 vb; vb.x = x2; vb.y = x3;
                *(float2*)(Cf + r0 * N + col) = va;
                *(float2*)(Cf + r1 * N + col) = vb;
            }
        }
    }
}

// ---------------------------------------------------------------------------
// Flash attention, fp32, causal (epilogue writes fp16 hi/lo)
// ---------------------------------------------------------------------------
#define SPAD 68
#define FLASH_SMEM (4 * 64 * SPAD * (int)sizeof(float))

__global__ __launch_bounds__(256)
void flash_kernel(const float* __restrict__ qkv, __half* __restrict__ zh,
                  __half* __restrict__ zl) {
    extern __shared__ float smf[];
    float* qs = smf;
    float* ks = smf + 64 * SPAD;
    float* vs = smf + 2 * 64 * SPAD;
    float* ps = smf + 3 * 64 * SPAD;

    const int qt = blockIdx.x, h = blockIdx.y, b = blockIdx.z;
    const int tid = threadIdx.x;
    const int tx = tid & 15, ty = tid >> 4;
    const int r0 = ty * 4, c0 = tx * 4;

    const float* base = qkv + (size_t)b * SS * QKVN;

    #pragma unroll
    for (int it = 0; it < 4; it++) {
        int i = tid + it * 256;
        int row = i >> 4;
        int c4 = (i & 15) * 4;
        float4 v = *(const float4*)(base + (size_t)(qt * 64 + row) * QKVN + h * 64 + c4);
        qs[(c4 + 0) * SPAD + row] = v.x;
        qs[(c4 + 1) * SPAD + row] = v.y;
        qs[(c4 + 2) * SPAD + row] = v.z;
        qs[(c4 + 3) * SPAD + row] = v.w;
    }

    float m_i[4], l_i[4], o[4][4];
    #pragma unroll
    for (int i = 0; i < 4; i++) {
        m_i[i] = -1e30f; l_i[i] = 0.f;
        #pragma unroll
        for (int j = 0; j < 4; j++) o[i][j] = 0.f;
    }
    __syncthreads();

    for (int kt = 0; kt <= qt; kt++) {
        #pragma unroll
        for (int it = 0; it < 4; it++) {
            int i = tid + it * 256;
            int row = i >> 4;
            int c4 = (i & 15) * 4;
            const float* kr = base + (size_t)(kt * 64 + row) * QKVN + h * 64;
            float4 kv = *(const float4*)(kr + DD + c4);
            ks[(c4 + 0) * SPAD + row] = kv.x;
            ks[(c4 + 1) * SPAD + row] = kv.y;
            ks[(c4 + 2) * SPAD + row] = kv.z;
            ks[(c4 + 3) * SPAD + row] = kv.w;
            *(float4*)(vs + row * SPAD + c4) = *(const float4*)(kr + 2 * DD + c4);
        }
        __syncthreads();

        float s[4][4];
        #pragma unroll
        for (int i = 0; i < 4; i++)
            #pragma unroll
            for (int j = 0; j < 4; j++) s[i][j] = 0.f;
        #pragma unroll 4
        for (int k = 0; k < 64; k++) {
            float qv[4], kv[4];
            #pragma unroll
            for (int i = 0; i < 4; i++) qv[i] = qs[k * SPAD + r0 + i];
            #pragma unroll
            for (int j = 0; j < 4; j++) kv[j] = ks[k * SPAD + c0 + j];
            #pragma unroll
            for (int i = 0; i < 4; i++)
                #pragma unroll
                for (int j = 0; j < 4; j++) s[i][j] += qv[i] * kv[j];
        }

        if (kt == qt) {
            #pragma unroll
            for (int i = 0; i < 4; i++)
                #pragma unroll
                for (int j = 0; j < 4; j++)
                    s[i][j] = (c0 + j <= r0 + i) ? s[i][j] * 0.125f : -1e30f;
        } else {
            #pragma unroll
            for (int i = 0; i < 4; i++)
                #pragma unroll
                for (int j = 0; j < 4; j++) s[i][j] *= 0.125f;
        }

        float mnew[4], rsum[4];
        #pragma unroll
        for (int i = 0; i < 4; i++) {
            float mx = fmaxf(fmaxf(s[i][0], s[i][1]), fmaxf(s[i][2], s[i][3]));
            #pragma unroll
            for (int off = 1; off < 16; off <<= 1)
                mx = fmaxf(mx, __shfl_xor_sync(0xffffffffu, mx, off));
            mnew[i] = fmaxf(m_i[i], mx);
        }
        #pragma unroll
        for (int i = 0; i < 4; i++) {
            float rs = 0.f;
            #pragma unroll
            for (int j = 0; j < 4; j++) {
                s[i][j] = __expf(s[i][j] - mnew[i]);
                rs += s[i][j];
            }
            #pragma unroll
            for (int off = 1; off < 16; off <<= 1)
                rs += __shfl_xor_sync(0xffffffffu, rs, off);
            rsum[i] = rs;
        }
        #pragma unroll
        for (int i = 0; i < 4; i++) {
            float alpha = __expf(m_i[i] - mnew[i]);
            l_i[i] = l_i[i] * alpha + rsum[i];
            m_i[i] = mnew[i];
            #pragma unroll
            for (int j = 0; j < 4; j++) o[i][j] *= alpha;
        }

        #pragma unroll
        for (int i = 0; i < 4; i++)
            #pragma unroll
            for (int j = 0; j < 4; j++)
                ps[(c0 + j) * SPAD + r0 + i] = s[i][j];
        __syncthreads();

        #pragma unroll 4
        for (int j = 0; j < 64; j++) {
            float pr[4], vv[4];
            #pragma unroll
            for (int i = 0; i < 4; i++) pr[i] = ps[j * SPAD + r0 + i];
            #pragma unroll
            for (int jj = 0; jj < 4; jj++) vv[jj] = vs[j * SPAD + c0 + jj];
            #pragma unroll
            for (int i = 0; i < 4; i++)
                #pragma unroll
                for (int jj = 0; jj < 4; jj++) o[i][jj] += pr[i] * vv[jj];
        }
        __syncthreads();
    }

    #pragma unroll
    for (int i = 0; i < 4; i++) {
        float invl = 1.f / l_i[i];
        size_t row = (size_t)(b * SS + qt * 64 + r0 + i);
        size_t off = row * DD + h * 64 + c0;
        float y0 = o[i][0] * invl, y1 = o[i][1] * invl;
        float y2 = o[i][2] * invl, y3 = o[i][3] * invl;
        __half h0, l0, h1, l1, h2, l2, h3, l3;
        split_h(y0, h0, l0); split_h(y1, h1, l1);
        split_h(y2, h2, l2); split_h(y3, h3, l3);
        *(__half2*)(zh + off)     = __halves2half2(h0, h1);
        *(__half2*)(zh + off + 2) = __halves2half2(h2, h3);
        *(__half2*)(zl + off)     = __halves2half2(l0, l1);
        *(__half2*)(zl + off + 2) = __halves2half2(l2, l3);
    }
}

// ---------------------------------------------------------------------------
// Launch
// ---------------------------------------------------------------------------
extern "C" void kernel_launch(void* const* d_in, const int* in_sizes, int n_in,
                              void* d_out, int out_size) {
    (void)in_sizes; (void)n_in; (void)out_size;
    const float* resid_pre = (const float*)d_in[0];
    const float* ln1_w = (const float*)d_in[1];
    const float* ln1_b = (const float*)d_in[2];
    const float* W_Q   = (const float*)d_in[3];
    const float* W_K   = (const float*)d_in[4];
    const float* W_V   = (const float*)d_in[5];
    const float* W_O   = (const float*)d_in[6];
    const float* b_Q   = (const float*)d_in[7];
    const float* b_K   = (const float*)d_in[8];
    const float* b_V   = (const float*)d_in[9];
    const float* b_O   = (const float*)d_in[10];
    const float* ln2_w = (const float*)d_in[11];
    const float* ln2_b = (const float*)d_in[12];
    const float* W_in  = (const float*)d_in[13];
    const float* b_in  = (const float*)d_in[14];
    const float* W_out = (const float*)d_in[15];
    const float* b_out = (const float*)d_in[16];
    float* out = (float*)d_out;

    __half *p_x1h, *p_x1l, *p_wqkvh, *p_wqkvl, *p_zh, *p_zl;
    __half *p_woh, *p_wol, *p_x2h, *p_x2l, *p_winh, *p_winl;
    __half *p_hh, *p_hl, *p_wouth, *p_woutl;
    float *p_bqkv, *p_qkv, *p_rmid;
    cudaGetSymbolAddress((void**)&p_x1h, g_x1h);     cudaGetSymbolAddress((void**)&p_x1l, g_x1l);
    cudaGetSymbolAddress((void**)&p_wqkvh, g_wqkvh); cudaGetSymbolAddress((void**)&p_wqkvl, g_wqkvl);
    cudaGetSymbolAddress((void**)&p_bqkv, g_bqkv);   cudaGetSymbolAddress((void**)&p_qkv, g_qkv);
    cudaGetSymbolAddress((void**)&p_zh, g_zh);       cudaGetSymbolAddress((void**)&p_zl, g_zl);
    cudaGetSymbolAddress((void**)&p_woh, g_woh);     cudaGetSymbolAddress((void**)&p_wol, g_wol);
    cudaGetSymbolAddress((void**)&p_rmid, g_rmid);
    cudaGetSymbolAddress((void**)&p_x2h, g_x2h);     cudaGetSymbolAddress((void**)&p_x2l, g_x2l);
    cudaGetSymbolAddress((void**)&p_winh, g_winh);   cudaGetSymbolAddress((void**)&p_winl, g_winl);
    cudaGetSymbolAddress((void**)&p_hh, g_hh);       cudaGetSymbolAddress((void**)&p_hl, g_hl);
    cudaGetSymbolAddress((void**)&p_wouth, g_wouth); cudaGetSymbolAddress((void**)&p_woutl, g_woutl);

    cudaFuncSetAttribute(flash_kernel, cudaFuncAttributeMaxDynamicSharedMemorySize, FLASH_SMEM);
    cudaFuncSetAttribute(gemm_hmma<0>, cudaFuncAttributeMaxDynamicSharedMemorySize, GEMM_SMEM);
    cudaFuncSetAttribute(gemm_hmma<1>, cudaFuncAttributeMaxDynamicSharedMemorySize, GEMM_SMEM);
    cudaFuncSetAttribute(gemm_hmma<2>, cudaFuncAttributeMaxDynamicSharedMemorySize, GEMM_SMEM);

    // weight conversions
    conv_wqkv<<<dim3(32, 16), 256>>>(W_Q, W_K, W_V);
    pack_bqkv<<<4, 256>>>(b_Q, b_K, b_V);
    conv_wT<<<dim3(DD / 32, DD / 32), dim3(32, 8)>>>(W_O, p_woh, p_wol, DD, DD);
    conv_wT<<<dim3(DMM / 32, DD / 32), dim3(32, 8)>>>(W_in, p_winh, p_winl, DD, DMM);
    conv_wT<<<dim3(DD / 32, DMM / 32), dim3(32, 8)>>>(W_out, p_wouth, p_woutl, DMM, DD);

    // LN1
    ln_kernel<<<BSS, 256>>>(resid_pre, ln1_w, ln1_b, p_x1h, p_x1l);

    // QKV projection: [4096,3072] fp32 out
    gemm_hmma<0><<<dim3(QKVN / 128, BSS / 128), 256, GEMM_SMEM>>>(
        p_x1h, p_x1l, p_wqkvh, p_wqkvl, p_bqkv, nullptr,
        p_qkv, nullptr, nullptr, BSS, QKVN, DD);

    // flash attention -> z hi/lo
    flash_kernel<<<dim3(SS / 64, HH, BB), 256, FLASH_SMEM>>>(p_qkv, p_zh, p_zl);

    // O projection + residual -> rmid fp32
    gemm_hmma<2><<<dim3(DD / 128, BSS / 128), 256, GEMM_SMEM>>>(
        p_zh, p_zl, p_woh, p_wol, b_O, resid_pre,
        p_rmid, nullptr, nullptr, BSS, DD, DD);

    // LN2
    ln_kernel<<<BSS, 256>>>(p_rmid, ln2_w, ln2_b, p_x2h, p_x2l);

    // MLP in + gelu -> h hi/lo
    gemm_hmma<1><<<dim3(DMM / 128, BSS / 128), 256, GEMM_SMEM>>>(
        p_x2h, p_x2l, p_winh, p_winl, b_in, nullptr,
        nullptr, p_hh, p_hl, BSS, DMM, DD);

    // MLP out + residual -> out fp32
    gemm_hmma<2><<<dim3(DD / 128, BSS / 128), 256, GEMM_SMEM>>>(
        p_hh, p_hl, p_wouth, p_woutl, b_out, p_rmid,
        out, nullptr, nullptr, BSS, DD, DMM);
}

// round 5
// speedup vs baseline: 3.1497x; 1.5030x over previous
#include <cuda_runtime.h>
#include <cuda_fp16.h>
#include <cstdint>
#include <cstddef>

// ---------------------------------------------------------------------------
// Problem constants
// ---------------------------------------------------------------------------
#define BB   2
#define SS   2048
#define DD   1024
#define HH   16
#define DHH  64
#define DMM  4096
#define BSS  (BB * SS)          // 4096 rows
#define QKVN (3 * DD)           // 3072
#define LN_EPS 1e-5f

// ---------------------------------------------------------------------------
// Scratch (static device globals; no allocations allowed)
// ---------------------------------------------------------------------------
__device__ __half g_x1h[BSS * DD], g_x1l[BSS * DD];
__device__ __half g_wqkvh[QKVN * DD], g_wqkvl[QKVN * DD];   // [N=3072,K=1024]
__device__ float  g_bqkv[QKVN];
__device__ __half g_qkvh[(size_t)BSS * QKVN];               // q(0.125-folded)|k|v hi
__device__ __half g_qkvl[(size_t)BSS * QKVN];               // lo
__device__ __half g_zh[BSS * DD], g_zl[BSS * DD];
__device__ __half g_woh[DD * DD], g_wol[DD * DD];           // [N=1024,K=1024]
__device__ float  g_rmid[BSS * DD];
__device__ __half g_x2h[BSS * DD], g_x2l[BSS * DD];
__device__ __half g_winh[DMM * DD], g_winl[DMM * DD];       // [N=4096,K=1024]
__device__ __half g_hh[(size_t)BSS * DMM], g_hl[(size_t)BSS * DMM];
__device__ __half g_wouth[DD * DMM], g_woutl[DD * DMM];     // [N=1024,K=4096]

// ---------------------------------------------------------------------------
// PTX helpers (baseline ISA only: ldmatrix / mma.sync / cp.async)
// ---------------------------------------------------------------------------
__device__ __forceinline__ uint32_t smem_u32(const void* p) {
    uint32_t a;
    asm("{ .reg .u64 t; cvta.to.shared.u64 t, %1; cvt.u32.u64 %0, t; }" : "=r"(a) : "l"(p));
    return a;
}
__device__ __forceinline__ void ldsm4(uint32_t& r0, uint32_t& r1, uint32_t& r2,
                                      uint32_t& r3, uint32_t a) {
    asm volatile("ldmatrix.sync.aligned.m8n8.x4.shared.b16 {%0,%1,%2,%3}, [%4];"
                 : "=r"(r0), "=r"(r1), "=r"(r2), "=r"(r3) : "r"(a));
}
__device__ __forceinline__ void ldsm4t(uint32_t& r0, uint32_t& r1, uint32_t& r2,
                                       uint32_t& r3, uint32_t a) {
    asm volatile("ldmatrix.sync.aligned.m8n8.x4.trans.shared.b16 {%0,%1,%2,%3}, [%4];"
                 : "=r"(r0), "=r"(r1), "=r"(r2), "=r"(r3) : "r"(a));
}
__device__ __forceinline__ void mma16816(float* c, const uint32_t* a, const uint32_t* b) {
    asm volatile(
        "mma.sync.aligned.m16n8k16.row.col.f32.f16.f16.f32 "
        "{%0,%1,%2,%3},{%4,%5,%6,%7},{%8,%9},{%0,%1,%2,%3};"
        : "+f"(c[0]), "+f"(c[1]), "+f"(c[2]), "+f"(c[3])
        : "r"(a[0]), "r"(a[1]), "r"(a[2]), "r"(a[3]), "r"(b[0]), "r"(b[1]));
}
__device__ __forceinline__ void mma2(float* c, const uint32_t* a, uint32_t b0, uint32_t b1) {
    asm volatile(
        "mma.sync.aligned.m16n8k16.row.col.f32.f16.f16.f32 "
        "{%0,%1,%2,%3},{%4,%5,%6,%7},{%8,%9},{%0,%1,%2,%3};"
        : "+f"(c[0]), "+f"(c[1]), "+f"(c[2]), "+f"(c[3])
        : "r"(a[0]), "r"(a[1]), "r"(a[2]), "r"(a[3]), "r"(b0), "r"(b1));
}
__device__ __forceinline__ void cp16(uint32_t d, const void* s) {
    asm volatile("cp.async.cg.shared.global [%0], [%1], 16;" :: "r"(d), "l"(s) : "memory");
}
#define CP_COMMIT() asm volatile("cp.async.commit_group;" ::: "memory")

__device__ __forceinline__ void split_h(float x, __half& hi, __half& lo) {
    hi = __float2half_rn(x);
    lo = __float2half_rn(x - __half2float(hi));
}
__device__ __forceinline__ uint32_t f2h2(float a, float b) {
    __half2 h = __floats2half2_rn(a, b);
    return *(uint32_t*)&h;
}

// ---------------------------------------------------------------------------
// Weight conversion kernels
// ---------------------------------------------------------------------------
__global__ __launch_bounds__(256)
void conv_wqkv(const float* __restrict__ WQ, const float* __restrict__ WK,
               const float* __restrict__ WV) {
    __shared__ float t[32][65];
    int h = blockIdx.y, k0 = blockIdx.x * 32, tid = threadIdx.x;
    const float* Ws[3] = {WQ, WK, WV};
    for (int s = 0; s < 3; s++) {
        const float* src = Ws[s] + (size_t)h * DD * DHH + (size_t)k0 * DHH;
        #pragma unroll
        for (int it = 0; it < 8; it++) {
            int idx = tid + it * 256;
            t[idx >> 6][idx & 63] = src[idx];
        }
        __syncthreads();
        #pragma unroll
        for (int it = 0; it < 8; it++) {
            int idx = tid + it * 256;
            int dh = idx >> 5, kk = idx & 31;
            float v = t[kk][dh];
            __half hi, lo; split_h(v, hi, lo);
            size_t n = (size_t)s * DD + h * 64 + dh;
            g_wqkvh[n * DD + k0 + kk] = hi;
            g_wqkvl[n * DD + k0 + kk] = lo;
        }
        __syncthreads();
    }
}

__global__ void pack_bqkv(const float* __restrict__ bQ, const float* __restrict__ bK,
                          const float* __restrict__ bV) {
    int i = blockIdx.x * blockDim.x + threadIdx.x;
    if (i < DD) {
        g_bqkv[i] = bQ[i];
        g_bqkv[DD + i] = bK[i];
        g_bqkv[2 * DD + i] = bV[i];
    }
}

__global__ __launch_bounds__(256)
void conv_wT(const float* __restrict__ W, __half* __restrict__ Bh,
             __half* __restrict__ Bl, int K, int N) {
    __shared__ float t[32][33];
    int n0 = blockIdx.x * 32, k0 = blockIdx.y * 32;
    int tx = threadIdx.x, ty = threadIdx.y;
    #pragma unroll
    for (int i = 0; i < 4; i++)
        t[ty + i * 8][tx] = W[(size_t)(k0 + ty + i * 8) * N + n0 + tx];
    __syncthreads();
    #pragma unroll
    for (int i = 0; i < 4; i++) {
        int n = n0 + ty + i * 8, k = k0 + tx;
        float v = t[tx][ty + i * 8];
        __half hi, lo; split_h(v, hi, lo);
        Bh[(size_t)n * K + k] = hi;
        Bl[(size_t)n * K + k] = lo;
    }
}

// ---------------------------------------------------------------------------
// LayerNorm -> fp16 hi/lo
// ---------------------------------------------------------------------------
__device__ __forceinline__ float block_sum(float v, float* red) {
    __syncthreads();
    int lane = threadIdx.x & 31, wid = threadIdx.x >> 5;
    #pragma unroll
    for (int o = 16; o > 0; o >>= 1) v += __shfl_xor_sync(0xffffffffu, v, o);
    if (lane == 0) red[wid] = v;
    __syncthreads();
    float t = (threadIdx.x < (blockDim.x >> 5)) ? red[threadIdx.x] : 0.f;
    if (wid == 0) {
        #pragma unroll
        for (int o = 16; o > 0; o >>= 1) t += __shfl_xor_sync(0xffffffffu, t, o);
        if (lane == 0) red[0] = t;
    }
    __syncthreads();
    return red[0];
}

__global__ __launch_bounds__(256)
void ln_kernel(const float* __restrict__ x, const float* __restrict__ w,
               const float* __restrict__ b, __half* __restrict__ oh,
               __half* __restrict__ ol) {
    __shared__ float row[DD];
    __shared__ float red[32];
    int r = blockIdx.x;
    const float* xr = x + (size_t)r * DD;
    float s = 0.f;
    for (int i = threadIdx.x; i < DD; i += 256) { float v = xr[i]; row[i] = v; s += v; }
    s = block_sum(s, red);
    float mean = s * (1.f / DD);
    float q = 0.f;
    for (int i = threadIdx.x; i < DD; i += 256) { float v = row[i] - mean; q += v * v; }
    q = block_sum(q, red);
    float inv = rsqrtf(q * (1.f / DD) + LN_EPS);
    for (int i = threadIdx.x; i < DD; i += 256) {
        float y = (row[i] - mean) * inv * w[i] + b[i];
        __half hi, lo; split_h(y, hi, lo);
        oh[(size_t)r * DD + i] = hi;
        ol[(size_t)r * DD + i] = lo;
    }
}

__device__ __forceinline__ float gelu_tanh(float x) {
    float x3 = x * x * x;
    return 0.5f * x * (1.f + tanhf(0.7978845608028654f * (x + 0.044715f * x3)));
}

// ---------------------------------------------------------------------------
// HMMA fp16-split GEMM (see R4). EPI: 0 bias->fp32 ; 1 bias+gelu->fp16 hi/lo ;
// 2 bias+residual->fp32 ; 3 bias (,*0.125 for first 8 col-blocks) -> fp16 hi/lo
// ---------------------------------------------------------------------------
#define OPD_BYTES 10240              // 128 rows * 80 B
#define BUF_BYTES (4 * OPD_BYTES)    // Ah | Al | Bh | Bl
#define GEMM_SMEM (2 * BUF_BYTES)    // 81920 B

template <int EPI>
__global__ __launch_bounds__(256, 2)
void gemm_hmma(const __half* __restrict__ Ah, const __half* __restrict__ Al,
               const __half* __restrict__ Bh, const __half* __restrict__ Bl,
               const float* __restrict__ bias, const float* __restrict__ R,
               float* __restrict__ Cf, __half* __restrict__ Chi,
               __half* __restrict__ Clo, int M, int N, int K) {
    extern __shared__ char sm[];
    const uint32_t sb = smem_u32(sm);
    const int tid = threadIdx.x;
    const int wid = tid >> 5, lid = tid & 31;
    const int warp_m = wid >> 2, warp_n = wid & 3;

    const char* src[4];
    src[0] = (const char*)(Ah + (size_t)blockIdx.y * 128 * K);
    src[1] = (const char*)(Al + (size_t)blockIdx.y * 128 * K);
    src[2] = (const char*)(Bh + (size_t)blockIdx.x * 128 * K);
    src[3] = (const char*)(Bl + (size_t)blockIdx.x * 128 * K);
    const size_t rowB = (size_t)K * 2;

    const int g = lid >> 3, li = lid & 7;
    const int a_row = (g & 1) * 8 + li, a_kb = (g >> 1) * 16;
    const int b_row = (g >> 1) * 8 + li, b_kb = (g & 1) * 16;

    float acc[4][4][4];
    #pragma unroll
    for (int mt = 0; mt < 4; mt++)
        #pragma unroll
        for (int nt = 0; nt < 4; nt++)
            #pragma unroll
            for (int e = 0; e < 4; e++) acc[mt][nt][e] = 0.f;

    const int T = K >> 5;

    #pragma unroll
    for (int pre = 0; pre < 2; pre++) {
        uint32_t dst = sb + pre * BUF_BYTES;
        int k0b = pre * 64;
        #pragma unroll
        for (int it = 0; it < 8; it++) {
            int c = tid + it * 256;
            int o = c >> 9, r = c & 511, row = r >> 2, kc = r & 3;
            cp16(dst + o * OPD_BYTES + row * 80 + kc * 16,
                 src[o] + (size_t)row * rowB + k0b + kc * 16);
        }
        CP_COMMIT();
    }

    for (int t = 0; t < T; t++) {
        if (t + 1 < T) { asm volatile("cp.async.wait_group 1;" ::: "memory"); }
        else           { asm volatile("cp.async.wait_group 0;" ::: "memory"); }
        __syncthreads();

        uint32_t buf = sb + (t & 1) * BUF_BYTES;
        uint32_t aH = buf + (warp_m * 64 + a_row) * 80 + a_kb;
        uint32_t aL = aH + OPD_BYTES;
        uint32_t bH = buf + 2 * OPD_BYTES + (warp_n * 32 + b_row) * 80 + b_kb;
        uint32_t bL = bH + OPD_BYTES;

        #pragma unroll
        for (int kk = 0; kk < 2; kk++) {
            uint32_t bh[4][2], bl[4][2];
            ldsm4(bh[0][0], bh[0][1], bh[1][0], bh[1][1], bH + kk * 32);
            ldsm4(bh[2][0], bh[2][1], bh[3][0], bh[3][1], bH + 16 * 80 + kk * 32);
            ldsm4(bl[0][0], bl[0][1], bl[1][0], bl[1][1], bL + kk * 32);
            ldsm4(bl[2][0], bl[2][1], bl[3][0], bl[3][1], bL + 16 * 80 + kk * 32);
            #pragma unroll
            for (int mt = 0; mt < 4; mt++) {
                uint32_t ah[4], al[4];
                ldsm4(ah[0], ah[1], ah[2], ah[3], aH + mt * 16 * 80 + kk * 32);
                ldsm4(al[0], al[1], al[2], al[3], aL + mt * 16 * 80 + kk * 32);
                #pragma unroll
                for (int nt = 0; nt < 4; nt++) {
                    mma16816(acc[mt][nt], ah, bh[nt]);
                    mma16816(acc[mt][nt], ah, bl[nt]);
                    mma16816(acc[mt][nt], al, bh[nt]);
                }
            }
        }
        __syncthreads();

        if (t + 2 < T) {
            uint32_t dst = sb + (t & 1) * BUF_BYTES;
            int k0b = (t + 2) * 64;
            #pragma unroll
            for (int it = 0; it < 8; it++) {
                int c = tid + it * 256;
                int o = c >> 9, r = c & 511, row = r >> 2, kc = r & 3;
                cp16(dst + o * OPD_BYTES + row * 80 + kc * 16,
                     src[o] + (size_t)row * rowB + k0b + kc * 16);
            }
            CP_COMMIT();
        }
    }

    const int group = lid >> 2, t4 = lid & 3;
    const size_t rbase = (size_t)blockIdx.y * 128 + warp_m * 64;
    const int cbase = blockIdx.x * 128 + warp_n * 32;
    #pragma unroll
    for (int mt = 0; mt < 4; mt++) {
        size_t r0 = rbase + mt * 16 + group;
        size_t r1 = r0 + 8;
        #pragma unroll
        for (int nt = 0; nt < 4; nt++) {
            int col = cbase + nt * 8 + t4 * 2;
            float* c = acc[mt][nt];
            float b0 = bias[col], b1 = bias[col + 1];
            float x0 = c[0] + b0, x1 = c[1] + b1;
            float x2 = c[2] + b0, x3 = c[3] + b1;
            if (EPI == 1 || EPI == 3) {
                if (EPI == 1) {
                    x0 = gelu_tanh(x0); x1 = gelu_tanh(x1);
                    x2 = gelu_tanh(x2); x3 = gelu_tanh(x3);
                } else {
                    float qsc = (blockIdx.x < 8) ? 0.125f : 1.0f;  // fold 1/sqrt(DH) into Q
                    x0 *= qsc; x1 *= qsc; x2 *= qsc; x3 *= qsc;
                }
                __half h0, l0, h1, l1, h2, l2, h3, l3;
                split_h(x0, h0, l0); split_h(x1, h1, l1);
                split_h(x2, h2, l2); split_h(x3, h3, l3);
                *(__half2*)(Chi + r0 * N + col) = __halves2half2(h0, h1);
                *(__half2*)(Clo + r0 * N + col) = __halves2half2(l0, l1);
                *(__half2*)(Chi + r1 * N + col) = __halves2half2(h2, h3);
                *(__half2*)(Clo + r1 * N + col) = __halves2half2(l2, l3);
            } else {
                if (EPI == 2) {
                    float2 ra = *(const float2*)(R + r0 * N + col);
                    float2 rb = *(const float2*)(R + r1 * N + col);
                    x0 += ra.x; x1 += ra.y; x2 += rb.x; x3 += rb.y;
                }
                float2 va; va.x = x0; va.y = x1;
                float2 vb; vb.x = x2; vb.y = x3;
                *(float2*)(Cf + r0 * N + col) = va;
                *(float2*)(Cf + r1 * N + col) = vb;
            }
        }
    }
}

// ---------------------------------------------------------------------------
// flash2: tensor-core causal flash attention.
// CTA = 128 q rows x (b,h). 8 warps x 16 rows. K-tiles of 64 keys.
// Scores: 3-term split (QhKh + QhKl + QlKh), scale pre-folded into Q.
// Softmax fp32 in C-fragments; P->fp16 reused as A-frags; PV: P*(Vh)+P*(Vl).
// smem pitch 144B (conflict-free ldmatrix); cp.async double-buffered K/V.
// ---------------------------------------------------------------------------
#define FPB 144
#define FL_QH 0
#define FL_QL 18432
#define FL_KV 36864
#define FL_TILE 9216
#define FL_BUF 36864
#define FLASH2_SMEM (FL_KV + 2 * FL_BUF)   // 110592

__device__ __forceinline__ void fl_load_kv(uint32_t sb, const __half* bh_,
                                           const __half* bl_, int kt, int bi, int tid) {
    uint32_t dst0 = sb + FL_KV + bi * FL_BUF;
    #pragma unroll
    for (int it = 0; it < 8; it++) {
        int idx = tid + it * 256;
        int reg = idx >> 9;                  // 0 Kh, 1 Kl, 2 Vh, 3 Vl
        int r = idx & 511;
        int row = r >> 3, c = r & 7;
        const __half* s = ((reg & 1) ? bl_ : bh_)
            + (size_t)(kt * 64 + row) * QKVN + ((reg >> 1) ? 2048 : 1024) + c * 8;
        cp16(dst0 + reg * FL_TILE + row * FPB + c * 16, s);
    }
    CP_COMMIT();
}

__global__ __launch_bounds__(256)
void flash2(const __half* __restrict__ qkvh, const __half* __restrict__ qkvl,
            __half* __restrict__ zh, __half* __restrict__ zl) {
    extern __shared__ char sm[];
    const uint32_t sb = smem_u32(sm);
    const int tid = threadIdx.x, wid = tid >> 5, lid = tid & 31;
    const int qt = (int)gridDim.x - 1 - (int)blockIdx.x;   // heavy tiles first
    const int h = blockIdx.y, b = blockIdx.z;

    const __half* bh_ = qkvh + (size_t)b * SS * QKVN + h * 64;
    const __half* bl_ = qkvl + (size_t)b * SS * QKVN + h * 64;

    // Q tile load (128 rows, hi+lo)
    #pragma unroll
    for (int it = 0; it < 8; it++) {
        int idx = tid + it * 256;
        int sel = idx >> 10;
        int r = idx & 1023;
        int row = r >> 3, c = r & 7;
        const __half* s = (sel ? bl_ : bh_) + (size_t)(qt * 128 + row) * QKVN + c * 8;
        cp16(sb + (sel ? FL_QL : FL_QH) + row * FPB + c * 16, s);
    }
    CP_COMMIT();
    fl_load_kv(sb, bh_, bl_, 0, 0, tid);

    asm volatile("cp.async.wait_group 1;" ::: "memory");  // Q done
    __syncthreads();

    // Q A-fragments (held in registers for the whole kernel)
    const int g2 = lid >> 3, li = lid & 7;
    const int a_row = (g2 & 1) * 8 + li, a_kb = (g2 >> 1) * 16;
    const uint32_t qa = sb + FL_QH + (wid * 16 + a_row) * FPB + a_kb;
    uint32_t qh[4][4], ql[4][4];
    #pragma unroll
    for (int kc = 0; kc < 4; kc++) {
        ldsm4(qh[kc][0], qh[kc][1], qh[kc][2], qh[kc][3], qa + kc * 32);
        ldsm4(ql[kc][0], ql[kc][1], ql[kc][2], ql[kc][3], qa + FL_QL + kc * 32);
    }

    float o[8][4];
    #pragma unroll
    for (int nt = 0; nt < 8; nt++)
        #pragma unroll
        for (int e = 0; e < 4; e++) o[nt][e] = 0.f;
    float m0 = -1e30f, m1 = -1e30f, l0 = 0.f, l1 = 0.f;

    const int gq = lid >> 2, t4 = lid & 3;
    const int row0g = qt * 128 + wid * 16 + gq;
    const int row1g = row0g + 8;
    const int nkt = 2 * qt + 2;

    const uint32_t kb_off = (uint32_t)(((g2 >> 1) * 8 + li) * FPB + (g2 & 1) * 16);
    const uint32_t v_off  = (uint32_t)(((g2 & 1) * 8 + li) * FPB + (g2 >> 1) * 16);

    for (int kt = 0; kt < nkt; kt++) {
        if (kt + 1 < nkt) {
            fl_load_kv(sb, bh_, bl_, kt + 1, (kt + 1) & 1, tid);
            asm volatile("cp.async.wait_group 1;" ::: "memory");
        } else {
            asm volatile("cp.async.wait_group 0;" ::: "memory");
        }
        __syncthreads();
        const uint32_t buf = sb + FL_KV + (kt & 1) * FL_BUF;

        // ---- scores S = Q K^T (3-term) ----
        float s[8][4];
        #pragma unroll
        for (int nt = 0; nt < 8; nt++)
            #pragma unroll
            for (int e = 0; e < 4; e++) s[nt][e] = 0.f;

        #pragma unroll
        for (int kc = 0; kc < 4; kc++) {
            #pragma unroll
            for (int ntp = 0; ntp < 4; ntp++) {
                uint32_t ka = buf + kb_off + ntp * 16 * FPB + kc * 32;
                uint32_t h0, h1, h2, h3, e0, e1, e2, e3;
                ldsm4(h0, h1, h2, h3, ka);
                ldsm4(e0, e1, e2, e3, ka + FL_TILE);
                mma2(s[2 * ntp],     qh[kc], h0, h1);
                mma2(s[2 * ntp],     qh[kc], e0, e1);
                mma2(s[2 * ntp],     ql[kc], h0, h1);
                mma2(s[2 * ntp + 1], qh[kc], h2, h3);
                mma2(s[2 * ntp + 1], qh[kc], e2, e3);
                mma2(s[2 * ntp + 1], ql[kc], h2, h3);
            }
        }

        // causal mask (only the two diagonal tiles)
        if (kt >= 2 * qt) {
            int colb = kt * 64 + 2 * t4;
            #pragma unroll
            for (int nt = 0; nt < 8; nt++) {
                int c0 = colb + nt * 8, c1 = c0 + 1;
                if (c0 > row0g) s[nt][0] = -1e30f;
                if (c1 > row0g) s[nt][1] = -1e30f;
                if (c0 > row1g) s[nt][2] = -1e30f;
                if (c1 > row1g) s[nt][3] = -1e30f;
            }
        }

        // ---- online softmax ----
        float tm0 = -1e30f, tm1 = -1e30f;
        #pragma unroll
        for (int nt = 0; nt < 8; nt++) {
            tm0 = fmaxf(tm0, fmaxf(s[nt][0], s[nt][1]));
            tm1 = fmaxf(tm1, fmaxf(s[nt][2], s[nt][3]));
        }
        tm0 = fmaxf(tm0, __shfl_xor_sync(0xffffffffu, tm0, 1));
        tm0 = fmaxf(tm0, __shfl_xor_sync(0xffffffffu, tm0, 2));
        tm1 = fmaxf(tm1, __shfl_xor_sync(0xffffffffu, tm1, 1));
        tm1 = fmaxf(tm1, __shfl_xor_sync(0xffffffffu, tm1, 2));
        float mn0 = fmaxf(m0, tm0), mn1 = fmaxf(m1, tm1);
        float al0 = __expf(m0 - mn0), al1 = __expf(m1 - mn1);
        m0 = mn0; m1 = mn1;

        float rs0 = 0.f, rs1 = 0.f;
        #pragma unroll
        for (int nt = 0; nt < 8; nt++) {
            s[nt][0] = __expf(s[nt][0] - mn0); rs0 += s[nt][0];
            s[nt][1] = __expf(s[nt][1] - mn0); rs0 += s[nt][1];
            s[nt][2] = __expf(s[nt][2] - mn1); rs1 += s[nt][2];
            s[nt][3] = __expf(s[nt][3] - mn1); rs1 += s[nt][3];
        }
        rs0 += __shfl_xor_sync(0xffffffffu, rs0, 1);
        rs0 += __shfl_xor_sync(0xffffffffu, rs0, 2);
        rs1 += __shfl_xor_sync(0xffffffffu, rs1, 1);
        rs1 += __shfl_xor_sync(0xffffffffu, rs1, 2);
        l0 = l0 * al0 + rs0;
        l1 = l1 * al1 + rs1;
        #pragma unroll
        for (int nt = 0; nt < 8; nt++) {
            o[nt][0] *= al0; o[nt][1] *= al0;
            o[nt][2] *= al1; o[nt][3] *= al1;
        }

        // pack P as A-fragments
        uint32_t pa[4][4];
        #pragma unroll
        for (int kc = 0; kc < 4; kc++) {
            pa[kc][0] = f2h2(s[2 * kc][0],     s[2 * kc][1]);
            pa[kc][1] = f2h2(s[2 * kc][2],     s[2 * kc][3]);
            pa[kc][2] = f2h2(s[2 * kc + 1][0], s[2 * kc + 1][1]);
            pa[kc][3] = f2h2(s[2 * kc + 1][2], s[2 * kc + 1][3]);
        }

        // ---- O += P V (V hi + V lo) ----
        #pragma unroll
        for (int kc = 0; kc < 4; kc++) {
            #pragma unroll
            for (int ntp = 0; ntp < 4; ntp++) {
                uint32_t va = buf + 2 * FL_TILE + kc * 16 * FPB + ntp * 32 + v_off;
                uint32_t h0, h1, h2, h3, e0, e1, e2, e3;
                ldsm4t(h0, h1, h2, h3, va);
                ldsm4t(e0, e1, e2, e3, va + FL_TILE);
                mma2(o[2 * ntp],     pa[kc], h0, h1);
                mma2(o[2 * ntp],     pa[kc], e0, e1);
                mma2(o[2 * ntp + 1], pa[kc], h2, h3);
                mma2(o[2 * ntp + 1], pa[kc], e2, e3);
            }
        }
        __syncthreads();   // protect buffer before next iteration's cp.async
    }

    // ---- epilogue: z = O / l, split to fp16 hi/lo ----
    float iv0 = 1.f / l0, iv1 = 1.f / l1;
    size_t r0 = (size_t)b * SS + qt * 128 + wid * 16 + gq;
    size_t r1 = r0 + 8;
    #pragma unroll
    for (int nt = 0; nt < 8; nt++) {
        int col = h * 64 + nt * 8 + 2 * t4;
        float y0 = o[nt][0] * iv0, y1 = o[nt][1] * iv0;
        float y2 = o[nt][2] * iv1, y3 = o[nt][3] * iv1;
        __half h0, l0h, h1, l1h, h2, l2h, h3, l3h;
        split_h(y0, h0, l0h); split_h(y1, h1, l1h);
        split_h(y2, h2, l2h); split_h(y3, h3, l3h);
        *(__half2*)(zh + r0 * DD + col) = __halves2half2(h0, h1);
        *(__half2*)(zl + r0 * DD + col) = __halves2half2(l0h, l1h);
        *(__half2*)(zh + r1 * DD + col) = __halves2half2(h2, h3);
        *(__half2*)(zl + r1 * DD + col) = __halves2half2(l2h, l3h);
    }
}

// ---------------------------------------------------------------------------
// Launch
// ---------------------------------------------------------------------------
extern "C" void kernel_launch(void* const* d_in, const int* in_sizes, int n_in,
                              void* d_out, int out_size) {
    (void)in_sizes; (void)n_in; (void)out_size;
    const float* resid_pre = (const float*)d_in[0];
    const float* ln1_w = (const float*)d_in[1];
    const float* ln1_b = (const float*)d_in[2];
    const float* W_Q   = (const float*)d_in[3];
    const float* W_K   = (const float*)d_in[4];
    const float* W_V   = (const float*)d_in[5];
    const float* W_O   = (const float*)d_in[6];
    const float* b_Q   = (const float*)d_in[7];
    const float* b_K   = (const float*)d_in[8];
    const float* b_V   = (const float*)d_in[9];
    const float* b_O   = (const float*)d_in[10];
    const float* ln2_w = (const float*)d_in[11];
    const float* ln2_b = (const float*)d_in[12];
    const float* W_in  = (const float*)d_in[13];
    const float* b_in  = (const float*)d_in[14];
    const float* W_out = (const float*)d_in[15];
    const float* b_out = (const float*)d_in[16];
    float* out = (float*)d_out;

    __half *p_x1h, *p_x1l, *p_wqkvh, *p_wqkvl, *p_qkvh, *p_qkvl, *p_zh, *p_zl;
    __half *p_woh, *p_wol, *p_x2h, *p_x2l, *p_winh, *p_winl;
    __half *p_hh, *p_hl, *p_wouth, *p_woutl;
    float *p_bqkv, *p_rmid;
    cudaGetSymbolAddress((void**)&p_x1h, g_x1h);     cudaGetSymbolAddress((void**)&p_x1l, g_x1l);
    cudaGetSymbolAddress((void**)&p_wqkvh, g_wqkvh); cudaGetSymbolAddress((void**)&p_wqkvl, g_wqkvl);
    cudaGetSymbolAddress((void**)&p_bqkv, g_bqkv);
    cudaGetSymbolAddress((void**)&p_qkvh, g_qkvh);   cudaGetSymbolAddress((void**)&p_qkvl, g_qkvl);
    cudaGetSymbolAddress((void**)&p_zh, g_zh);       cudaGetSymbolAddress((void**)&p_zl, g_zl);
    cudaGetSymbolAddress((void**)&p_woh, g_woh);     cudaGetSymbolAddress((void**)&p_wol, g_wol);
    cudaGetSymbolAddress((void**)&p_rmid, g_rmid);
    cudaGetSymbolAddress((void**)&p_x2h, g_x2h);     cudaGetSymbolAddress((void**)&p_x2l, g_x2l);
    cudaGetSymbolAddress((void**)&p_winh, g_winh);   cudaGetSymbolAddress((void**)&p_winl, g_winl);
    cudaGetSymbolAddress((void**)&p_hh, g_hh);       cudaGetSymbolAddress((void**)&p_hl, g_hl);
    cudaGetSymbolAddress((void**)&p_wouth, g_wouth); cudaGetSymbolAddress((void**)&p_woutl, g_woutl);

    cudaFuncSetAttribute(flash2, cudaFuncAttributeMaxDynamicSharedMemorySize, FLASH2_SMEM);
    cudaFuncSetAttribute(gemm_hmma<1>, cudaFuncAttributeMaxDynamicSharedMemorySize, GEMM_SMEM);
    cudaFuncSetAttribute(gemm_hmma<2>, cudaFuncAttributeMaxDynamicSharedMemorySize, GEMM_SMEM);
    cudaFuncSetAttribute(gemm_hmma<3>, cudaFuncAttributeMaxDynamicSharedMemorySize, GEMM_SMEM);

    // weight conversions
    conv_wqkv<<<dim3(32, 16), 256>>>(W_Q, W_K, W_V);
    pack_bqkv<<<4, 256>>>(b_Q, b_K, b_V);
    conv_wT<<<dim3(DD / 32, DD / 32), dim3(32, 8)>>>(W_O, p_woh, p_wol, DD, DD);
    conv_wT<<<dim3(DMM / 32, DD / 32), dim3(32, 8)>>>(W_in, p_winh, p_winl, DD, DMM);
    conv_wT<<<dim3(DD / 32, DMM / 32), dim3(32, 8)>>>(W_out, p_wouth, p_woutl, DMM, DD);

    // LN1
    ln_kernel<<<BSS, 256>>>(resid_pre, ln1_w, ln1_b, p_x1h, p_x1l);

    // QKV projection -> fp16 hi/lo (Q scaled by 0.125)
    gemm_hmma<3><<<dim3(QKVN / 128, BSS / 128), 256, GEMM_SMEM>>>(
        p_x1h, p_x1l, p_wqkvh, p_wqkvl, p_bqkv, nullptr,
        nullptr, p_qkvh, p_qkvl, BSS, QKVN, DD);

    // flash attention (tensor cores) -> z hi/lo
    flash2<<<dim3(SS / 128, HH, BB), 256, FLASH2_SMEM>>>(p_qkvh, p_qkvl, p_zh, p_zl);

    // O projection + residual -> rmid fp32
    gemm_hmma<2><<<dim3(DD / 128, BSS / 128), 256, GEMM_SMEM>>>(
        p_zh, p_zl, p_woh, p_wol, b_O, resid_pre,
        p_rmid, nullptr, nullptr, BSS, DD, DD);

    // LN2
    ln_kernel<<<BSS, 256>>>(p_rmid, ln2_w, ln2_b, p_x2h, p_x2l);

    // MLP in + gelu -> h hi/lo
    gemm_hmma<1><<<dim3(DMM / 128, BSS / 128), 256, GEMM_SMEM>>>(
        p_x2h, p_x2l, p_winh, p_winl, b_in, nullptr,
        nullptr, p_hh, p_hl, BSS, DMM, DD);

    // MLP out + residual -> out fp32
    gemm_hmma<2><<<dim3(DD / 128, BSS / 128), 256, GEMM_SMEM>>>(
        p_hh, p_hl, p_wouth, p_woutl, b_out, p_rmid,
        out, nullptr, nullptr, BSS, DD, DMM);
}

// round 6
// speedup vs baseline: 6.7028x; 2.1281x over previous
#include <cuda_runtime.h>
#include <cuda_fp16.h>
#include <cstdint>
#include <cstddef>

// ---------------------------------------------------------------------------
// Problem constants
// ---------------------------------------------------------------------------
#define BB   2
#define SS   2048
#define DD   1024
#define HH   16
#define DHH  64
#define DMM  4096
#define BSS  (BB * SS)          // 4096 rows
#define QKVN (3 * DD)           // 3072
#define LN_EPS 1e-5f

// ---------------------------------------------------------------------------
// Scratch (static device globals; fp16 single-precision path, fp32 accum)
// ---------------------------------------------------------------------------
__device__ __half g_x1[BSS * DD];                 // LN1 out
__device__ __half g_wqkv[QKVN * DD];              // [N=3072,K=1024]
__device__ float  g_bqkv[QKVN];
__device__ __half g_qkv[(size_t)BSS * QKVN];      // q(0.125-folded)|k|v
__device__ __half g_z[BSS * DD];                  // attention out
__device__ __half g_wo[DD * DD];                  // [N=1024,K=1024]
__device__ float  g_rmid[BSS * DD];
__device__ __half g_x2[BSS * DD];                 // LN2 out
__device__ __half g_win[DMM * DD];                // [N=4096,K=1024]
__device__ __half g_h[(size_t)BSS * DMM];         // MLP hidden
__device__ __half g_wout[DD * DMM];               // [N=1024,K=4096]

// ---------------------------------------------------------------------------
// PTX helpers (baseline ISA: ldmatrix / mma.sync / cp.async)
// ---------------------------------------------------------------------------
__device__ __forceinline__ uint32_t smem_u32(const void* p) {
    uint32_t a;
    asm("{ .reg .u64 t; cvta.to.shared.u64 t, %1; cvt.u32.u64 %0, t; }" : "=r"(a) : "l"(p));
    return a;
}
__device__ __forceinline__ void ldsm4(uint32_t& r0, uint32_t& r1, uint32_t& r2,
                                      uint32_t& r3, uint32_t a) {
    asm volatile("ldmatrix.sync.aligned.m8n8.x4.shared.b16 {%0,%1,%2,%3}, [%4];"
                 : "=r"(r0), "=r"(r1), "=r"(r2), "=r"(r3) : "r"(a));
}
__device__ __forceinline__ void ldsm4t(uint32_t& r0, uint32_t& r1, uint32_t& r2,
                                       uint32_t& r3, uint32_t a) {
    asm volatile("ldmatrix.sync.aligned.m8n8.x4.trans.shared.b16 {%0,%1,%2,%3}, [%4];"
                 : "=r"(r0), "=r"(r1), "=r"(r2), "=r"(r3) : "r"(a));
}
__device__ __forceinline__ void mma16816(float* c, const uint32_t* a, const uint32_t* b) {
    asm volatile(
        "mma.sync.aligned.m16n8k16.row.col.f32.f16.f16.f32 "
        "{%0,%1,%2,%3},{%4,%5,%6,%7},{%8,%9},{%0,%1,%2,%3};"
        : "+f"(c[0]), "+f"(c[1]), "+f"(c[2]), "+f"(c[3])
        : "r"(a[0]), "r"(a[1]), "r"(a[2]), "r"(a[3]), "r"(b[0]), "r"(b[1]));
}
__device__ __forceinline__ void mma2(float* c, const uint32_t* a, uint32_t b0, uint32_t b1) {
    asm volatile(
        "mma.sync.aligned.m16n8k16.row.col.f32.f16.f16.f32 "
        "{%0,%1,%2,%3},{%4,%5,%6,%7},{%8,%9},{%0,%1,%2,%3};"
        : "+f"(c[0]), "+f"(c[1]), "+f"(c[2]), "+f"(c[3])
        : "r"(a[0]), "r"(a[1]), "r"(a[2]), "r"(a[3]), "r"(b0), "r"(b1));
}
__device__ __forceinline__ void cp16(uint32_t d, const void* s) {
    asm volatile("cp.async.cg.shared.global [%0], [%1], 16;" :: "r"(d), "l"(s) : "memory");
}
#define CP_COMMIT() asm volatile("cp.async.commit_group;" ::: "memory")

__device__ __forceinline__ uint32_t f2h2(float a, float b) {
    __half2 h = __floats2half2_rn(a, b);
    return *(uint32_t*)&h;
}

// ---------------------------------------------------------------------------
// Weight conversion kernels
// ---------------------------------------------------------------------------
// W_Q/K/V [H,D,DH] -> wqkv [N=3072,K=1024] fp16. block 256, grid (32 ktiles, 16 h)
__global__ __launch_bounds__(256)
void conv_wqkv(const float* __restrict__ WQ, const float* __restrict__ WK,
               const float* __restrict__ WV) {
    __shared__ float t[32][65];
    int h = blockIdx.y, k0 = blockIdx.x * 32, tid = threadIdx.x;
    const float* Ws[3] = {WQ, WK, WV};
    for (int s = 0; s < 3; s++) {
        const float* src = Ws[s] + (size_t)h * DD * DHH + (size_t)k0 * DHH;
        #pragma unroll
        for (int it = 0; it < 8; it++) {
            int idx = tid + it * 256;
            t[idx >> 6][idx & 63] = src[idx];
        }
        __syncthreads();
        #pragma unroll
        for (int it = 0; it < 8; it++) {
            int idx = tid + it * 256;
            int dh = idx >> 5, kk = idx & 31;
            size_t n = (size_t)s * DD + h * 64 + dh;
            g_wqkv[n * DD + k0 + kk] = __float2half_rn(t[kk][dh]);
        }
        __syncthreads();
    }
}

__global__ void pack_bqkv(const float* __restrict__ bQ, const float* __restrict__ bK,
                          const float* __restrict__ bV) {
    int i = blockIdx.x * blockDim.x + threadIdx.x;
    if (i < DD) {
        g_bqkv[i] = bQ[i];
        g_bqkv[DD + i] = bK[i];
        g_bqkv[2 * DD + i] = bV[i];
    }
}

// transpose: W fp32 [K,N] -> B fp16 [N,K]. block (32,8), grid (N/32, K/32)
__global__ __launch_bounds__(256)
void conv_wT(const float* __restrict__ W, __half* __restrict__ B, int K, int N) {
    __shared__ float t[32][33];
    int n0 = blockIdx.x * 32, k0 = blockIdx.y * 32;
    int tx = threadIdx.x, ty = threadIdx.y;
    #pragma unroll
    for (int i = 0; i < 4; i++)
        t[ty + i * 8][tx] = W[(size_t)(k0 + ty + i * 8) * N + n0 + tx];
    __syncthreads();
    #pragma unroll
    for (int i = 0; i < 4; i++) {
        int n = n0 + ty + i * 8, k = k0 + tx;
        B[(size_t)n * K + k] = __float2half_rn(t[tx][ty + i * 8]);
    }
}

// ---------------------------------------------------------------------------
// LayerNorm -> fp16
// ---------------------------------------------------------------------------
__device__ __forceinline__ float block_sum(float v, float* red) {
    __syncthreads();
    int lane = threadIdx.x & 31, wid = threadIdx.x >> 5;
    #pragma unroll
    for (int o = 16; o > 0; o >>= 1) v += __shfl_xor_sync(0xffffffffu, v, o);
    if (lane == 0) red[wid] = v;
    __syncthreads();
    float t = (threadIdx.x < (blockDim.x >> 5)) ? red[threadIdx.x] : 0.f;
    if (wid == 0) {
        #pragma unroll
        for (int o = 16; o > 0; o >>= 1) t += __shfl_xor_sync(0xffffffffu, t, o);
        if (lane == 0) red[0] = t;
    }
    __syncthreads();
    return red[0];
}

__global__ __launch_bounds__(256)
void ln_kernel(const float* __restrict__ x, const float* __restrict__ w,
               const float* __restrict__ b, __half* __restrict__ o) {
    __shared__ float row[DD];
    __shared__ float red[32];
    int r = blockIdx.x;
    const float* xr = x + (size_t)r * DD;
    float s = 0.f;
    for (int i = threadIdx.x; i < DD; i += 256) { float v = xr[i]; row[i] = v; s += v; }
    s = block_sum(s, red);
    float mean = s * (1.f / DD);
    float q = 0.f;
    for (int i = threadIdx.x; i < DD; i += 256) { float v = row[i] - mean; q += v * v; }
    q = block_sum(q, red);
    float inv = rsqrtf(q * (1.f / DD) + LN_EPS);
    for (int i = threadIdx.x; i < DD; i += 256)
        o[(size_t)r * DD + i] = __float2half_rn((row[i] - mean) * inv * w[i] + b[i]);
}

__device__ __forceinline__ float gelu_tanh(float x) {
    float x3 = x * x * x;
    return 0.5f * x * (1.f + tanhf(0.7978845608028654f * (x + 0.044715f * x3)));
}

// ---------------------------------------------------------------------------
// HMMA fp16 GEMM: C[M,N] = A[M,K] @ B[N,K]^T + bias ; fp32 accumulate.
// 128x128 CTA tile, K-tile 32, 8 warps (2x4), warp tile 64x32, m16n8k16.
// smem rows padded to 80B (conflict-free ldmatrix). Double-buffered cp.async.
// EPI: 1 bias+gelu -> fp16 ; 2 bias+residual -> fp32 ; 3 bias (Q cols *0.125) -> fp16
// ---------------------------------------------------------------------------
#define OPD_BYTES 10240              // 128 rows * 80 B
#define BUF_BYTES (2 * OPD_BYTES)    // A | B
#define GEMM_SMEM (2 * BUF_BYTES)    // 40960 B

template <int EPI>
__global__ __launch_bounds__(256, 2)
void gemm_hmma(const __half* __restrict__ A, const __half* __restrict__ B,
               const float* __restrict__ bias, const float* __restrict__ R,
               float* __restrict__ Cf, __half* __restrict__ Ch,
               int M, int N, int K) {
    extern __shared__ char sm[];
    const uint32_t sb = smem_u32(sm);
    const int tid = threadIdx.x;
    const int wid = tid >> 5, lid = tid & 31;
    const int warp_m = wid >> 2, warp_n = wid & 3;

    const char* src[2];
    src[0] = (const char*)(A + (size_t)blockIdx.y * 128 * K);
    src[1] = (const char*)(B + (size_t)blockIdx.x * 128 * K);
    const size_t rowB = (size_t)K * 2;

    const int g = lid >> 3, li = lid & 7;
    const int a_row = (g & 1) * 8 + li, a_kb = (g >> 1) * 16;
    const int b_row = (g >> 1) * 8 + li, b_kb = (g & 1) * 16;

    float acc[4][4][4];
    #pragma unroll
    for (int mt = 0; mt < 4; mt++)
        #pragma unroll
        for (int nt = 0; nt < 4; nt++)
            #pragma unroll
            for (int e = 0; e < 4; e++) acc[mt][nt][e] = 0.f;

    const int T = K >> 5;

    #pragma unroll
    for (int pre = 0; pre < 2; pre++) {
        uint32_t dst = sb + pre * BUF_BYTES;
        int k0b = pre * 64;
        #pragma unroll
        for (int it = 0; it < 4; it++) {
            int c = tid + it * 256;
            int o = c >> 9, r = c & 511, row = r >> 2, kc = r & 3;
            cp16(dst + o * OPD_BYTES + row * 80 + kc * 16,
                 src[o] + (size_t)row * rowB + k0b + kc * 16);
        }
        CP_COMMIT();
    }

    for (int t = 0; t < T; t++) {
        if (t + 1 < T) { asm volatile("cp.async.wait_group 1;" ::: "memory"); }
        else           { asm volatile("cp.async.wait_group 0;" ::: "memory"); }
        __syncthreads();

        uint32_t buf = sb + (t & 1) * BUF_BYTES;
        uint32_t aP = buf + (warp_m * 64 + a_row) * 80 + a_kb;
        uint32_t bP = buf + OPD_BYTES + (warp_n * 32 + b_row) * 80 + b_kb;

        #pragma unroll
        for (int kk = 0; kk < 2; kk++) {
            uint32_t bh[4][2];
            ldsm4(bh[0][0], bh[0][1], bh[1][0], bh[1][1], bP + kk * 32);
            ldsm4(bh[2][0], bh[2][1], bh[3][0], bh[3][1], bP + 16 * 80 + kk * 32);
            #pragma unroll
            for (int mt = 0; mt < 4; mt++) {
                uint32_t ah[4];
                ldsm4(ah[0], ah[1], ah[2], ah[3], aP + mt * 16 * 80 + kk * 32);
                #pragma unroll
                for (int nt = 0; nt < 4; nt++)
                    mma16816(acc[mt][nt], ah, bh[nt]);
            }
        }
        __syncthreads();

        if (t + 2 < T) {
            uint32_t dst = sb + (t & 1) * BUF_BYTES;
            int k0b = (t + 2) * 64;
            #pragma unroll
            for (int it = 0; it < 4; it++) {
                int c = tid + it * 256;
                int o = c >> 9, r = c & 511, row = r >> 2, kc = r & 3;
                cp16(dst + o * OPD_BYTES + row * 80 + kc * 16,
                     src[o] + (size_t)row * rowB + k0b + kc * 16);
            }
            CP_COMMIT();
        }
    }

    const int group = lid >> 2, t4 = lid & 3;
    const size_t rbase = (size_t)blockIdx.y * 128 + warp_m * 64;
    const int cbase = blockIdx.x * 128 + warp_n * 32;
    #pragma unroll
    for (int mt = 0; mt < 4; mt++) {
        size_t r0 = rbase + mt * 16 + group;
        size_t r1 = r0 + 8;
        #pragma unroll
        for (int nt = 0; nt < 4; nt++) {
            int col = cbase + nt * 8 + t4 * 2;
            float* c = acc[mt][nt];
            float b0 = bias[col], b1 = bias[col + 1];
            float x0 = c[0] + b0, x1 = c[1] + b1;
            float x2 = c[2] + b0, x3 = c[3] + b1;
            if (EPI == 1 || EPI == 3) {
                if (EPI == 1) {
                    x0 = gelu_tanh(x0); x1 = gelu_tanh(x1);
                    x2 = gelu_tanh(x2); x3 = gelu_tanh(x3);
                } else {
                    float qsc = (blockIdx.x < 8) ? 0.125f : 1.0f;  // fold 1/sqrt(DH) into Q
                    x0 *= qsc; x1 *= qsc; x2 *= qsc; x3 *= qsc;
                }
                *(__half2*)(Ch + r0 * N + col) = __floats2half2_rn(x0, x1);
                *(__half2*)(Ch + r1 * N + col) = __floats2half2_rn(x2, x3);
            } else {
                float2 ra = *(const float2*)(R + r0 * N + col);
                float2 rb = *(const float2*)(R + r1 * N + col);
                x0 += ra.x; x1 += ra.y; x2 += rb.x; x3 += rb.y;
                float2 va; va.x = x0; va.y = x1;
                float2 vb; vb.x = x2; vb.y = x3;
                *(float2*)(Cf + r0 * N + col) = va;
                *(float2*)(Cf + r1 * N + col) = vb;
            }
        }
    }
}

// ---------------------------------------------------------------------------
// flash2: tensor-core causal flash attention, fp16 operands, fp32 softmax/acc.
// CTA = 128 q rows x (b,h). 8 warps x 16 rows. K-tiles of 64 keys.
// Q scale pre-folded. P fp16 reused directly as A-frags (no smem round-trip).
// smem pitch 144B (conflict-free ldmatrix); cp.async double-buffered K/V.
// ---------------------------------------------------------------------------
#define FPB 144
#define FL_KV 18432                  // Q tile: 128*144
#define FL_TILE 9216                 // one 64-row K or V tile
#define FL_BUF 18432                 // K | V
#define FLASH2_SMEM (FL_KV + 2 * FL_BUF)   // 55296

__device__ __forceinline__ void fl_load_kv(uint32_t sb, const __half* base,
                                           int kt, int bi, int tid) {
    uint32_t dst0 = sb + FL_KV + bi * FL_BUF;
    #pragma unroll
    for (int it = 0; it < 4; it++) {
        int idx = tid + it * 256;
        int reg = idx >> 9;                  // 0 K, 1 V
        int r = idx & 511;
        int row = r >> 3, c = r & 7;
        const __half* s = base + (size_t)(kt * 64 + row) * QKVN + DD + reg * DD + c * 8;
        cp16(dst0 + reg * FL_TILE + row * FPB + c * 16, s);
    }
    CP_COMMIT();
}

__global__ __launch_bounds__(256, 2)
void flash2(const __half* __restrict__ qkv, __half* __restrict__ z) {
    extern __shared__ char sm[];
    const uint32_t sb = smem_u32(sm);
    const int tid = threadIdx.x, wid = tid >> 5, lid = tid & 31;
    const int qt = (int)gridDim.x - 1 - (int)blockIdx.x;   // heavy tiles first
    const int h = blockIdx.y, b = blockIdx.z;

    const __half* base = qkv + (size_t)b * SS * QKVN + h * 64;

    // Q tile load (128 rows)
    #pragma unroll
    for (int it = 0; it < 4; it++) {
        int idx = tid + it * 256;
        int row = idx >> 3, c = idx & 7;
        cp16(sb + row * FPB + c * 16, base + (size_t)(qt * 128 + row) * QKVN + c * 8);
    }
    CP_COMMIT();
    fl_load_kv(sb, base, 0, 0, tid);

    asm volatile("cp.async.wait_group 1;" ::: "memory");  // Q done
    __syncthreads();

    // Q A-fragments held in registers
    const int g2 = lid >> 3, li = lid & 7;
    const int a_row = (g2 & 1) * 8 + li, a_kb = (g2 >> 1) * 16;
    const uint32_t qa = sb + (wid * 16 + a_row) * FPB + a_kb;
    uint32_t qh[4][4];
    #pragma unroll
    for (int kc = 0; kc < 4; kc++)
        ldsm4(qh[kc][0], qh[kc][1], qh[kc][2], qh[kc][3], qa + kc * 32);

    float o[8][4];
    #pragma unroll
    for (int nt = 0; nt < 8; nt++)
        #pragma unroll
        for (int e = 0; e < 4; e++) o[nt][e] = 0.f;
    float m0 = -1e30f, m1 = -1e30f, l0 = 0.f, l1 = 0.f;

    const int gq = lid >> 2, t4 = lid & 3;
    const int row0g = qt * 128 + wid * 16 + gq;
    const int row1g = row0g + 8;
    const int nkt = 2 * qt + 2;

    const uint32_t kb_off = (uint32_t)(((g2 >> 1) * 8 + li) * FPB + (g2 & 1) * 16);
    const uint32_t v_off  = (uint32_t)(((g2 & 1) * 8 + li) * FPB + (g2 >> 1) * 16);

    for (int kt = 0; kt < nkt; kt++) {
        if (kt + 1 < nkt) {
            fl_load_kv(sb, base, kt + 1, (kt + 1) & 1, tid);
            asm volatile("cp.async.wait_group 1;" ::: "memory");
        } else {
            asm volatile("cp.async.wait_group 0;" ::: "memory");
        }
        __syncthreads();
        const uint32_t buf = sb + FL_KV + (kt & 1) * FL_BUF;

        // ---- scores S = Q K^T ----
        float s[8][4];
        #pragma unroll
        for (int nt = 0; nt < 8; nt++)
            #pragma unroll
            for (int e = 0; e < 4; e++) s[nt][e] = 0.f;

        #pragma unroll
        for (int kc = 0; kc < 4; kc++) {
            #pragma unroll
            for (int ntp = 0; ntp < 4; ntp++) {
                uint32_t ka = buf + kb_off + ntp * 16 * FPB + kc * 32;
                uint32_t h0, h1, h2, h3;
                ldsm4(h0, h1, h2, h3, ka);
                mma2(s[2 * ntp],     qh[kc], h0, h1);
                mma2(s[2 * ntp + 1], qh[kc], h2, h3);
            }
        }

        // causal mask (only the two diagonal tiles)
        if (kt >= 2 * qt) {
            int colb = kt * 64 + 2 * t4;
            #pragma unroll
            for (int nt = 0; nt < 8; nt++) {
                int c0 = colb + nt * 8, c1 = c0 + 1;
                if (c0 > row0g) s[nt][0] = -1e30f;
                if (c1 > row0g) s[nt][1] = -1e30f;
                if (c0 > row1g) s[nt][2] = -1e30f;
                if (c1 > row1g) s[nt][3] = -1e30f;
            }
        }

        // ---- online softmax ----
        float tm0 = -1e30f, tm1 = -1e30f;
        #pragma unroll
        for (int nt = 0; nt < 8; nt++) {
            tm0 = fmaxf(tm0, fmaxf(s[nt][0], s[nt][1]));
            tm1 = fmaxf(tm1, fmaxf(s[nt][2], s[nt][3]));
        }
        tm0 = fmaxf(tm0, __shfl_xor_sync(0xffffffffu, tm0, 1));
        tm0 = fmaxf(tm0, __shfl_xor_sync(0xffffffffu, tm0, 2));
        tm1 = fmaxf(tm1, __shfl_xor_sync(0xffffffffu, tm1, 1));
        tm1 = fmaxf(tm1, __shfl_xor_sync(0xffffffffu, tm1, 2));
        float mn0 = fmaxf(m0, tm0), mn1 = fmaxf(m1, tm1);
        float al0 = __expf(m0 - mn0), al1 = __expf(m1 - mn1);
        m0 = mn0; m1 = mn1;

        float rs0 = 0.f, rs1 = 0.f;
        #pragma unroll
        for (int nt = 0; nt < 8; nt++) {
            s[nt][0] = __expf(s[nt][0] - mn0); rs0 += s[nt][0];
            s[nt][1] = __expf(s[nt][1] - mn0); rs0 += s[nt][1];
            s[nt][2] = __expf(s[nt][2] - mn1); rs1 += s[nt][2];
            s[nt][3] = __expf(s[nt][3] - mn1); rs1 += s[nt][3];
        }
        rs0 += __shfl_xor_sync(0xffffffffu, rs0, 1);
        rs0 += __shfl_xor_sync(0xffffffffu, rs0, 2);
        rs1 += __shfl_xor_sync(0xffffffffu, rs1, 1);
        rs1 += __shfl_xor_sync(0xffffffffu, rs1, 2);
        l0 = l0 * al0 + rs0;
        l1 = l1 * al1 + rs1;
        #pragma unroll
        for (int nt = 0; nt < 8; nt++) {
            o[nt][0] *= al0; o[nt][1] *= al0;
            o[nt][2] *= al1; o[nt][3] *= al1;
        }

        // pack P as A-fragments
        uint32_t pa[4][4];
        #pragma unroll
        for (int kc = 0; kc < 4; kc++) {
            pa[kc][0] = f2h2(s[2 * kc][0],     s[2 * kc][1]);
            pa[kc][1] = f2h2(s[2 * kc][2],     s[2 * kc][3]);
            pa[kc][2] = f2h2(s[2 * kc + 1][0], s[2 * kc + 1][1]);
            pa[kc][3] = f2h2(s[2 * kc + 1][2], s[2 * kc + 1][3]);
        }

        // ---- O += P V ----
        #pragma unroll
        for (int kc = 0; kc < 4; kc++) {
            #pragma unroll
            for (int ntp = 0; ntp < 4; ntp++) {
                uint32_t va = buf + FL_TILE + kc * 16 * FPB + ntp * 32 + v_off;
                uint32_t h0, h1, h2, h3;
                ldsm4t(h0, h1, h2, h3, va);
                mma2(o[2 * ntp],     pa[kc], h0, h1);
                mma2(o[2 * ntp + 1], pa[kc], h2, h3);
            }
        }
        __syncthreads();   // protect buffer before next iteration's cp.async
    }

    // ---- epilogue: z = O / l ----
    float iv0 = 1.f / l0, iv1 = 1.f / l1;
    size_t r0 = (size_t)b * SS + qt * 128 + wid * 16 + gq;
    size_t r1 = r0 + 8;
    #pragma unroll
    for (int nt = 0; nt < 8; nt++) {
        int col = h * 64 + nt * 8 + 2 * t4;
        *(__half2*)(z + r0 * DD + col) = __floats2half2_rn(o[nt][0] * iv0, o[nt][1] * iv0);
        *(__half2*)(z + r1 * DD + col) = __floats2half2_rn(o[nt][2] * iv1, o[nt][3] * iv1);
    }
}

// ---------------------------------------------------------------------------
// Launch
// ---------------------------------------------------------------------------
extern "C" void kernel_launch(void* const* d_in, const int* in_sizes, int n_in,
                              void* d_out, int out_size) {
    (void)in_sizes; (void)n_in; (void)out_size;
    const float* resid_pre = (const float*)d_in[0];
    const float* ln1_w = (const float*)d_in[1];
    const float* ln1_b = (const float*)d_in[2];
    const float* W_Q   = (const float*)d_in[3];
    const float* W_K   = (const float*)d_in[4];
    const float* W_V   = (const float*)d_in[5];
    const float* W_O   = (const float*)d_in[6];
    const float* b_Q   = (const float*)d_in[7];
    const float* b_K   = (const float*)d_in[8];
    const float* b_V   = (const float*)d_in[9];
    const float* b_O   = (const float*)d_in[10];
    const float* ln2_w = (const float*)d_in[11];
    const float* ln2_b = (const float*)d_in[12];
    const float* W_in  = (const float*)d_in[13];
    const float* b_in  = (const float*)d_in[14];
    const float* W_out = (const float*)d_in[15];
    const float* b_out = (const float*)d_in[16];
    float* out = (float*)d_out;

    __half *p_x1, *p_wqkv, *p_qkv, *p_z, *p_wo, *p_x2, *p_win, *p_h, *p_wout;
    float *p_bqkv, *p_rmid;
    cudaGetSymbolAddress((void**)&p_x1, g_x1);
    cudaGetSymbolAddress((void**)&p_wqkv, g_wqkv);
    cudaGetSymbolAddress((void**)&p_bqkv, g_bqkv);
    cudaGetSymbolAddress((void**)&p_qkv, g_qkv);
    cudaGetSymbolAddress((void**)&p_z, g_z);
    cudaGetSymbolAddress((void**)&p_wo, g_wo);
    cudaGetSymbolAddress((void**)&p_rmid, g_rmid);
    cudaGetSymbolAddress((void**)&p_x2, g_x2);
    cudaGetSymbolAddress((void**)&p_win, g_win);
    cudaGetSymbolAddress((void**)&p_h, g_h);
    cudaGetSymbolAddress((void**)&p_wout, g_wout);

    cudaFuncSetAttribute(flash2, cudaFuncAttributeMaxDynamicSharedMemorySize, FLASH2_SMEM);
    cudaFuncSetAttribute(gemm_hmma<1>, cudaFuncAttributeMaxDynamicSharedMemorySize, GEMM_SMEM);
    cudaFuncSetAttribute(gemm_hmma<2>, cudaFuncAttributeMaxDynamicSharedMemorySize, GEMM_SMEM);
    cudaFuncSetAttribute(gemm_hmma<3>, cudaFuncAttributeMaxDynamicSharedMemorySize, GEMM_SMEM);

    // weight conversions
    conv_wqkv<<<dim3(32, 16), 256>>>(W_Q, W_K, W_V);
    pack_bqkv<<<4, 256>>>(b_Q, b_K, b_V);
    conv_wT<<<dim3(DD / 32, DD / 32), dim3(32, 8)>>>(W_O, p_wo, DD, DD);
    conv_wT<<<dim3(DMM / 32, DD / 32), dim3(32, 8)>>>(W_in, p_win, DD, DMM);
    conv_wT<<<dim3(DD / 32, DMM / 32), dim3(32, 8)>>>(W_out, p_wout, DMM, DD);

    // LN1
    ln_kernel<<<BSS, 256>>>(resid_pre, ln1_w, ln1_b, p_x1);

    // QKV projection -> fp16 (Q scaled by 0.125)
    gemm_hmma<3><<<dim3(QKVN / 128, BSS / 128), 256, GEMM_SMEM>>>(
        p_x1, p_wqkv, p_bqkv, nullptr, nullptr, p_qkv, BSS, QKVN, DD);

    // flash attention (tensor cores) -> z
    flash2<<<dim3(SS / 128, HH, BB), 256, FLASH2_SMEM>>>(p_qkv, p_z);

    // O projection + residual -> rmid fp32
    gemm_hmma<2><<<dim3(DD / 128, BSS / 128), 256, GEMM_SMEM>>>(
        p_z, p_wo, b_O, resid_pre, p_rmid, nullptr, BSS, DD, DD);

    // LN2
    ln_kernel<<<BSS, 256>>>(p_rmid, ln2_w, ln2_b, p_x2);

    // MLP in + gelu -> h fp16
    gemm_hmma<1><<<dim3(DMM / 128, BSS / 128), 256, GEMM_SMEM>>>(
        p_x2, p_win, b_in, nullptr, nullptr, p_h, BSS, DMM, DD);

    // MLP out + residual -> out fp32
    gemm_hmma<2><<<dim3(DD / 128, BSS / 128), 256, GEMM_SMEM>>>(
        p_h, p_wout, b_out, p_rmid, out, nullptr, BSS, DD, DMM);
}